// round 9
// baseline (speedup 1.0000x reference)
#include <cuda_runtime.h>
#include <math.h>
#include <stdint.h>

#define B 16
#define N 512
#define D 768
#define H 12
#define DK 64
#define ND 32
#define ROWS (B * N)
#define OUT_ELEMS ((size_t)B * N * D)
#define ATT_ELEMS ((size_t)B * H * N * N)

// ---------------- scratch ----------------
__device__ float g_x[ROWS * D];
__device__ float g_q[ROWS * D];
__device__ float g_k[ROWS * D];
__device__ float g_v[ROWS * D];
__device__ float g_ao[ROWS * D];
__device__ float g_wt[4 * D * D];
__device__ int g_px[ROWS];
__device__ int g_py[ROWS];

__device__ __forceinline__ float to_tf32(float x) {
    uint32_t u;
    asm("cvt.rna.tf32.f32 %0, %1;" : "=r"(u) : "f"(x));
    return __uint_as_float(u);
}
__device__ __forceinline__ uint32_t smem_u32(const void* p) {
    uint32_t a;
    asm("{ .reg .u64 t; cvta.to.shared.u64 t, %1; cvt.u32.u64 %0, t; }" : "=r"(a) : "l"(p));
    return a;
}
#define CP_ASYNC16(dst, src) asm volatile("cp.async.cg.shared.global [%0], [%1], 16;" :: "r"(dst), "l"(src) : "memory")
#define CP_COMMIT()          asm volatile("cp.async.commit_group;" ::: "memory")
#define CP_WAIT(nn)          asm volatile("cp.async.wait_group %0;" :: "n"(nn) : "memory")

__device__ __forceinline__ void mma8(float* d, const uint32_t* a, const uint32_t* b) {
    asm volatile("mma.sync.aligned.m16n8k8.row.col.f32.tf32.tf32.f32 "
                 "{%0,%1,%2,%3}, {%4,%5,%6,%7}, {%8,%9}, {%0,%1,%2,%3};"
                 : "+f"(d[0]), "+f"(d[1]), "+f"(d[2]), "+f"(d[3])
                 : "r"(a[0]), "r"(a[1]), "r"(a[2]), "r"(a[3]), "r"(b[0]), "r"(b[1]));
}

// ---------------- LayerNorm (writes tf32-rounded) ----------------
__global__ void __launch_bounds__(256) ln_kernel(const float* __restrict__ f,
                                                 const float* __restrict__ gamma,
                                                 const float* __restrict__ beta) {
    int row = blockIdx.x;
    int t = threadIdx.x;
    const float* x = f + (size_t)row * D;
    float v[3];
    float s = 0.f, s2 = 0.f;
#pragma unroll
    for (int i = 0; i < 3; i++) {
        v[i] = x[t + i * 256];
        s += v[i];
        s2 += v[i] * v[i];
    }
    __shared__ float redA[8], redB[8];
#pragma unroll
    for (int o = 16; o; o >>= 1) {
        s += __shfl_xor_sync(~0u, s, o);
        s2 += __shfl_xor_sync(~0u, s2, o);
    }
    if ((t & 31) == 0) { redA[t >> 5] = s; redB[t >> 5] = s2; }
    __syncthreads();
    if (t < 32) {
        float a = (t < 8) ? redA[t] : 0.f;
        float c = (t < 8) ? redB[t] : 0.f;
#pragma unroll
        for (int o = 4; o; o >>= 1) {
            a += __shfl_xor_sync(~0u, a, o);
            c += __shfl_xor_sync(~0u, c, o);
        }
        if (t == 0) { redA[0] = a; redB[0] = c; }
    }
    __syncthreads();
    float mu = redA[0] * (1.0f / D);
    float var = redB[0] * (1.0f / D) - mu * mu;
    float rstd = rsqrtf(var + 1e-5f);
    float* xo = g_x + (size_t)row * D;
#pragma unroll
    for (int i = 0; i < 3; i++) {
        int c = t + i * 256;
        xo[c] = to_tf32((v[i] - mu) * rstd * gamma[c] + beta[c]);
    }
}

__global__ void __launch_bounds__(256) cvt_w(const float* __restrict__ Wq,
                                             const float* __restrict__ Wk,
                                             const float* __restrict__ Wv,
                                             const float* __restrict__ Wo) {
    int i = blockIdx.x * 256 + threadIdx.x;
    int z = blockIdx.y;
    const float* src = (z == 0) ? Wq : (z == 1) ? Wk : (z == 2) ? Wv : Wo;
    g_wt[(size_t)z * D * D + i] = to_tf32(src[i]);
}

__global__ void patch_kernel(const float* __restrict__ boxes,
                             const int* __restrict__ iszs) {
    int idx = blockIdx.x * 256 + threadIdx.x;
    if (idx >= ROWS) return;
    int b = idx >> 9;
    float w = (float)iszs[b * 4 + 0];
    float h = (float)iszs[b * 4 + 1];
    const float* bx = boxes + (size_t)idx * 4;
    float p0 = bx[0] * w, p1 = bx[1] * h, p2 = bx[2] * w, p3 = bx[3] * h;
    float spw = floorf(w / 11.0f);
    float sph = floorf(h / 11.0f);
    float cx = floorf((p0 + p2) * 0.5f);
    float cy = floorf((p1 + p3) * 0.5f);
    int px = 0, py = 0;
    bool fx = false, fy = false;
#pragma unroll
    for (int j = 0; j < 11; j++) {
        float jl = (float)j, jh = (float)(j + 1);
        float lo = jl * spw, hi = jh * spw;
        if (!fx && lo <= cx && cx <= hi) { px = j; fx = true; }
        float lo2 = jl * sph, hi2 = jh * sph;
        if (!fy && lo2 <= cy && cy <= hi2) { py = j; fy = true; }
    }
    g_px[idx] = px;
    g_py[idx] = py;
}

// ================ mma.sync tf32 GEMM: C[8192,768] = A @ W^T + bias ================
// BM=128, BN=256, BK=32. 16 warps (4x4), warp tile 32x64 (2 m-tiles x 8 n-tiles).
#define BM 128
#define BN 256
#define BK 32
#define PADK 36
#define AF (BM * PADK)                 // 4608 floats
#define BF (BN * PADK)                 // 9216 floats
#define SSTRIDE (AF + BF)              // 13824 floats per stage
#define NCHUNK (D / BK)                // 24
#define GEMM_SMEM (2 * SSTRIDE * 4)    // 110592 bytes
#define GT 512

__global__ void __launch_bounds__(GT, 1)
gemm_mma(const float* __restrict__ Aglob,
         const float* __restrict__ b0v, float* __restrict__ o0,
         const float* __restrict__ b1v, float* __restrict__ o1,
         const float* __restrict__ b2v, float* __restrict__ o2,
         int wsel, int head_layout) {
    extern __shared__ float smf[];
    uint32_t smb = smem_u32(smf);
    int tid = threadIdx.x;
    int z = blockIdx.z;
    const float* Wm = g_wt + (size_t)(wsel + z) * D * D;
    const float* bias = (z == 0) ? b0v : (z == 1) ? b1v : b2v;
    float* outp = (z == 0) ? o0 : (z == 1) ? o1 : o2;

    int r0 = blockIdx.y * BM;
    int c0 = blockIdx.x * BN;

    int lane = tid & 31, wid = tid >> 5;
    int wm = wid >> 2, wn = wid & 3;       // 4 x 4
    int g = lane >> 2, t = lane & 3;

    float acc[2][8][4];
#pragma unroll
    for (int i = 0; i < 2; i++)
#pragma unroll
        for (int j = 0; j < 8; j++)
#pragma unroll
            for (int r = 0; r < 4; r++) acc[i][j][r] = 0.f;

#define STAGE_CHUNK(cc, sbase)                                                      \
    do {                                                                            \
        uint32_t ab = (sbase);                                                      \
        uint32_t bb = (sbase) + AF * 4;                                             \
        _Pragma("unroll")                                                           \
        for (int i = 0; i < 2; i++) {                                               \
            int f = tid + i * GT;                                                   \
            int row = f >> 3, seg = f & 7;                                          \
            CP_ASYNC16(ab + (uint32_t)(row * PADK + seg * 4) * 4,                   \
                       Aglob + (size_t)(r0 + row) * D + (cc) * BK + seg * 4);       \
        }                                                                           \
        _Pragma("unroll")                                                           \
        for (int i = 0; i < 4; i++) {                                               \
            int f = tid + i * GT;                                                   \
            int row = f >> 3, seg = f & 7;                                          \
            CP_ASYNC16(bb + (uint32_t)(row * PADK + seg * 4) * 4,                   \
                       Wm + (size_t)(c0 + row) * D + (cc) * BK + seg * 4);          \
        }                                                                           \
        CP_COMMIT();                                                                \
    } while (0)

    STAGE_CHUNK(0, smb);

    for (int c = 0; c < NCHUNK; ++c) {
        if (c + 1 < NCHUNK) {
            STAGE_CHUNK(c + 1, smb + ((c + 1) & 1) * (SSTRIDE * 4));
            CP_WAIT(1);
        } else {
            CP_WAIT(0);
        }
        __syncthreads();

        const float* As = smf + (c & 1) * SSTRIDE;
        const float* Bs = As + AF;
#pragma unroll
        for (int ks = 0; ks < 4; ++ks) {
            int k = ks * 8;
            uint32_t af[2][4], bf[8][2];
#pragma unroll
            for (int mt = 0; mt < 2; mt++) {
                int m = wm * 32 + mt * 16 + g;
                af[mt][0] = __float_as_uint(As[m * PADK + k + t]);
                af[mt][1] = __float_as_uint(As[(m + 8) * PADK + k + t]);
                af[mt][2] = __float_as_uint(As[m * PADK + k + t + 4]);
                af[mt][3] = __float_as_uint(As[(m + 8) * PADK + k + t + 4]);
            }
#pragma unroll
            for (int nt = 0; nt < 8; nt++) {
                int n = wn * 64 + nt * 8 + g;
                bf[nt][0] = __float_as_uint(Bs[n * PADK + k + t]);
                bf[nt][1] = __float_as_uint(Bs[n * PADK + k + t + 4]);
            }
#pragma unroll
            for (int mt = 0; mt < 2; mt++)
#pragma unroll
                for (int nt = 0; nt < 8; nt++)
                    mma8(acc[mt][nt], af[mt], bf[nt]);
        }
        __syncthreads();
    }

#pragma unroll
    for (int mt = 0; mt < 2; mt++) {
#pragma unroll
        for (int nt = 0; nt < 8; nt++) {
            int cg = c0 + wn * 64 + nt * 8 + 2 * t;
            float b0 = bias[cg], b1 = bias[cg + 1];
#pragma unroll
            for (int half = 0; half < 2; half++) {
                int rg = r0 + wm * 32 + mt * 16 + g + half * 8;
                float v0 = acc[mt][nt][half * 2 + 0] + b0;
                float v1 = acc[mt][nt][half * 2 + 1] + b1;
                float* dst;
                if (head_layout) {
                    int bb = rg >> 9, n = rg & 511;
                    int hh = cg >> 6, dk = cg & 63;
                    dst = outp + (((size_t)(bb * H + hh) * N + n) * DK) + dk;
                    *(float2*)dst = make_float2(to_tf32(v0), to_tf32(v1));
                } else {
                    dst = outp + (size_t)rg * D + cg;
                    *(float2*)dst = make_float2(v0, v1);
                }
            }
        }
    }
}

// ================ attention with mma.sync tf32 + fused distance bias ================
// 512 threads, 16 warps (4x4). CTA = one (b,h) x 64 q rows.
#define AT 512
#define PADA 68
#define PADS 516
#define QS_OFF 0
#define KB0_OFF (64 * PADA)
#define KB1_OFF (2 * 64 * PADA)
#define SC_OFF  (3 * 64 * PADA)
#define LUT_OFF (SC_OFF + 64 * PADS)          // 441 floats
#define PK_OFF  (LUT_OFF + 448)               // 512 u16 => 256 floats
#define ATT_SMEM ((PK_OFF + 256) * 4)

__device__ __forceinline__ void load_chunk64(uint32_t dst_base, const float* src) {
    int tid = threadIdx.x;
#pragma unroll
    for (int it = 0; it < 2; ++it) {
        int idx = tid + it * AT;
        int row = idx >> 4, seg = idx & 15;
        CP_ASYNC16(dst_base + (uint32_t)(row * PADA + seg * 4) * 4, src + idx * 4);
    }
}

__global__ void __launch_bounds__(AT, 1) attn_mma(const float* __restrict__ dist_emb,
                                                  float* __restrict__ att_out) {
    extern __shared__ float sm[];
    uint32_t smb = smem_u32(sm);
    float* Qs = sm + QS_OFF;
    float* Sc = sm + SC_OFF;
    float* lut = sm + LUT_OFF;
    unsigned short* pk = (unsigned short*)(sm + PK_OFF);

    int tid = threadIdx.x;
    int bh = blockIdx.y;
    int b = bh / H;
    int h = bh - b * H;
    int q0 = blockIdx.x * 64;

    const float* Qg = g_q + ((size_t)bh * N + q0) * DK;
    const float* Kg = g_k + (size_t)bh * N * DK;
    const float* Vg = g_v + (size_t)bh * N * DK;

    int lane = tid & 31, wid = tid >> 5;
    int wm = wid >> 2, wn = wid & 3;      // 4 x 4
    int g = lane >> 2, t = lane & 3;
    const float scale = 0.125f;

    // prologue: Q + K chunk 0
    load_chunk64(smb + QS_OFF * 4, Qg);
    load_chunk64(smb + KB0_OFF * 4, Kg);
    CP_COMMIT();

    // distance-bias LUT (441 entries) + packed patch coords
    if (tid < 441) {
        int dyc = tid / 21 - 10, dxc = tid % 21 - 10;
        int bin = (int)(sqrtf((float)(dxc * dxc + dyc * dyc)) * 2.0f);
        lut[tid] = dist_emb[bin * H + h];
    }
    pk[tid] = (unsigned short)(g_py[b * N + tid] * 21 + g_px[b * N + tid]);

    // ---------- phase 1: S = Q K^T * scale ----------
    // warp tile: 16 q-rows (wm) x 16 k-cols (wn) within each 64-col chunk
    for (int kt = 0; kt < 8; ++kt) {
        if (kt < 7) {
            load_chunk64(smb + (((kt + 1) & 1) ? KB1_OFF : KB0_OFF) * 4, Kg + (kt + 1) * 4096);
            CP_COMMIT();
            CP_WAIT(1);
        } else {
            CP_WAIT(0);
        }
        __syncthreads();
        const float* Ks = sm + ((kt & 1) ? KB1_OFF : KB0_OFF);
        float acc[2][4];
#pragma unroll
        for (int j = 0; j < 2; j++)
#pragma unroll
            for (int r = 0; r < 4; r++) acc[j][r] = 0.f;
#pragma unroll
        for (int ks = 0; ks < 8; ++ks) {
            int k = ks * 8;
            uint32_t af[4], bf[2][2];
            {
                int m = wm * 16 + g;
                af[0] = __float_as_uint(Qs[m * PADA + k + t]);
                af[1] = __float_as_uint(Qs[(m + 8) * PADA + k + t]);
                af[2] = __float_as_uint(Qs[m * PADA + k + t + 4]);
                af[3] = __float_as_uint(Qs[(m + 8) * PADA + k + t + 4]);
            }
#pragma unroll
            for (int nt = 0; nt < 2; nt++) {
                int n = wn * 16 + nt * 8 + g;
                bf[nt][0] = __float_as_uint(Ks[n * PADA + k + t]);
                bf[nt][1] = __float_as_uint(Ks[n * PADA + k + t + 4]);
            }
#pragma unroll
            for (int nt = 0; nt < 2; nt++)
                mma8(acc[nt], af, bf[nt]);
        }
#pragma unroll
        for (int nt = 0; nt < 2; nt++) {
            int row = wm * 16 + g;
            int col = kt * 64 + wn * 16 + nt * 8 + 2 * t;
            *(float2*)&Sc[row * PADS + col] =
                make_float2(acc[nt][0] * scale, acc[nt][1] * scale);
            *(float2*)&Sc[(row + 8) * PADS + col] =
                make_float2(acc[nt][2] * scale, acc[nt][3] * scale);
        }
        __syncthreads();
    }

    // ---------- phase 2: softmax + LUT bias, write att, tf32 P into Sc ----------
#pragma unroll
    for (int rr = 0; rr < 4; rr++) {
        int qi = wid * 4 + rr;
        int qg = q0 + qi;
        int coff = 220 - (int)pk[qg];
        float* srow = Sc + qi * PADS;
        float m = -1e30f;
        for (int kk = lane; kk < N; kk += 32) {
            float s = srow[kk] + lut[(int)pk[kk] + coff];
            srow[kk] = s;
            m = fmaxf(m, s);
        }
#pragma unroll
        for (int o = 16; o; o >>= 1) m = fmaxf(m, __shfl_xor_sync(~0u, m, o));
        float ssum = 0.f;
        for (int kk = lane; kk < N; kk += 32) {
            float e = __expf(srow[kk] - m);
            srow[kk] = e;
            ssum += e;
        }
#pragma unroll
        for (int o = 16; o; o >>= 1) ssum += __shfl_xor_sync(~0u, ssum, o);
        float inv = 1.0f / ssum;
        float* arow = att_out + ((size_t)bh * N + qg) * N;
        for (int kk = lane; kk < N; kk += 32) {
            float p = srow[kk] * inv;
            arow[kk] = p;
            srow[kk] = to_tf32(p);
        }
    }

    // ---------- phase 3: O = P V ----------
    load_chunk64(smb + KB0_OFF * 4, Vg);
    CP_COMMIT();
    float oacc[2][4];
#pragma unroll
    for (int j = 0; j < 2; j++)
#pragma unroll
        for (int r = 0; r < 4; r++) oacc[j][r] = 0.f;

    for (int kt = 0; kt < 8; ++kt) {
        if (kt < 7) {
            load_chunk64(smb + (((kt + 1) & 1) ? KB1_OFF : KB0_OFF) * 4, Vg + (kt + 1) * 4096);
            CP_COMMIT();
            CP_WAIT(1);
        } else {
            CP_WAIT(0);
        }
        __syncthreads();
        const float* Vs = sm + ((kt & 1) ? KB1_OFF : KB0_OFF);
#pragma unroll
        for (int ks = 0; ks < 8; ++ks) {
            int k = ks * 8;
            uint32_t af[4], bf[2][2];
            {
                int m = wm * 16 + g;
                int sb = m * PADS + kt * 64 + k;
                af[0] = __float_as_uint(Sc[sb + t]);
                af[1] = __float_as_uint(Sc[sb + 8 * PADS + t]);
                af[2] = __float_as_uint(Sc[sb + t + 4]);
                af[3] = __float_as_uint(Sc[sb + 8 * PADS + t + 4]);
            }
#pragma unroll
            for (int nt = 0; nt < 2; nt++) {
                int n = wn * 16 + nt * 8 + g;
                bf[nt][0] = __float_as_uint(Vs[(k + t) * PADA + n]);
                bf[nt][1] = __float_as_uint(Vs[(k + t + 4) * PADA + n]);
            }
#pragma unroll
            for (int nt = 0; nt < 2; nt++)
                mma8(oacc[nt], af, bf[nt]);
        }
        __syncthreads();
    }

#pragma unroll
    for (int nt = 0; nt < 2; nt++) {
        int dk = wn * 16 + nt * 8 + 2 * t;
#pragma unroll
        for (int half = 0; half < 2; half++) {
            int qg = q0 + wm * 16 + g + half * 8;
            float* dst = g_ao + ((size_t)(b * N + qg)) * D + h * DK + dk;
            *(float2*)dst = make_float2(to_tf32(oacc[nt][half * 2 + 0]),
                                        to_tf32(oacc[nt][half * 2 + 1]));
        }
    }
}

// ---------------- launch ----------------
extern "C" void kernel_launch(void* const* d_in, const int* in_sizes, int n_in,
                              void* d_out, int out_size) {
    const float* features = (const float*)d_in[0];
    const float* boxes    = (const float*)d_in[1];
    const int*   iszs     = (const int*)  d_in[2];
    const float* Wq = (const float*)d_in[3];
    const float* bq = (const float*)d_in[4];
    const float* Wk = (const float*)d_in[5];
    const float* bk = (const float*)d_in[6];
    const float* Wv = (const float*)d_in[7];
    const float* bv = (const float*)d_in[8];
    const float* Wo = (const float*)d_in[9];
    const float* bo = (const float*)d_in[10];
    const float* gamma = (const float*)d_in[11];
    const float* beta  = (const float*)d_in[12];
    const float* dist_emb = (const float*)d_in[13];

    float* out = (float*)d_out;
    float* att = ((size_t)out_size >= OUT_ELEMS + ATT_ELEMS) ? out + OUT_ELEMS : out;

    cudaFuncSetAttribute(attn_mma, cudaFuncAttributeMaxDynamicSharedMemorySize, ATT_SMEM);
    cudaFuncSetAttribute(gemm_mma, cudaFuncAttributeMaxDynamicSharedMemorySize, GEMM_SMEM);

    float *gx, *gq, *gk, *gv, *gao;
    cudaGetSymbolAddress((void**)&gx, g_x);
    cudaGetSymbolAddress((void**)&gq, g_q);
    cudaGetSymbolAddress((void**)&gk, g_k);
    cudaGetSymbolAddress((void**)&gv, g_v);
    cudaGetSymbolAddress((void**)&gao, g_ao);

    ln_kernel<<<ROWS, 256>>>(features, gamma, beta);
    cvt_w<<<dim3((D * D) / 256, 4), 256>>>(Wq, Wk, Wv, Wo);
    patch_kernel<<<(ROWS + 255) / 256, 256>>>(boxes, iszs);

    dim3 gq3(D / BN, ROWS / BM, 3);
    gemm_mma<<<gq3, GT, GEMM_SMEM>>>(gx, bq, gq, bk, gk, bv, gv, 0, 1);

    dim3 ga(N / 64, B * H);
    attn_mma<<<ga, AT, ATT_SMEM>>>(dist_emb, att);

    dim3 go3(D / BN, ROWS / BM, 1);
    gemm_mma<<<go3, GT, GEMM_SMEM>>>(gao, bo, out, bo, out, bo, out, 3, 0);
}

// round 11
// speedup vs baseline: 1.0368x; 1.0368x over previous
#include <cuda_runtime.h>
#include <math.h>
#include <stdint.h>

#define B 16
#define N 512
#define D 768
#define H 12
#define DK 64
#define ND 32
#define ROWS (B * N)
#define OUT_ELEMS ((size_t)B * N * D)
#define ATT_ELEMS ((size_t)B * H * N * N)

// ---------------- scratch ----------------
__device__ float g_x[ROWS * D];
__device__ float g_q[ROWS * D];
__device__ float g_k[ROWS * D];
__device__ float g_v[ROWS * D];
__device__ float g_ao[ROWS * D];
__device__ float g_wt[4 * D * D];
__device__ int g_px[ROWS];
__device__ int g_py[ROWS];

__device__ __forceinline__ float to_tf32(float x) {
    uint32_t u;
    asm("cvt.rna.tf32.f32 %0, %1;" : "=r"(u) : "f"(x));
    return __uint_as_float(u);
}
__device__ __forceinline__ uint32_t smem_u32(const void* p) {
    uint32_t a;
    asm("{ .reg .u64 t; cvta.to.shared.u64 t, %1; cvt.u32.u64 %0, t; }" : "=r"(a) : "l"(p));
    return a;
}
#define CP_ASYNC16(dst, src) asm volatile("cp.async.cg.shared.global [%0], [%1], 16;" :: "r"(dst), "l"(src) : "memory")
#define CP_COMMIT()          asm volatile("cp.async.commit_group;" ::: "memory")
#define CP_WAIT(nn)          asm volatile("cp.async.wait_group %0;" :: "n"(nn) : "memory")

__device__ __forceinline__ void mma8(float* d, const uint32_t* a, const uint32_t* b) {
    asm volatile("mma.sync.aligned.m16n8k8.row.col.f32.tf32.tf32.f32 "
                 "{%0,%1,%2,%3}, {%4,%5,%6,%7}, {%8,%9}, {%0,%1,%2,%3};"
                 : "+f"(d[0]), "+f"(d[1]), "+f"(d[2]), "+f"(d[3])
                 : "r"(a[0]), "r"(a[1]), "r"(a[2]), "r"(a[3]), "r"(b[0]), "r"(b[1]));
}

// ---------------- LayerNorm (writes tf32-rounded) ----------------
__global__ void __launch_bounds__(256) ln_kernel(const float* __restrict__ f,
                                                 const float* __restrict__ gamma,
                                                 const float* __restrict__ beta) {
    int row = blockIdx.x;
    int t = threadIdx.x;
    const float* x = f + (size_t)row * D;
    float v[3];
    float s = 0.f, s2 = 0.f;
#pragma unroll
    for (int i = 0; i < 3; i++) {
        v[i] = x[t + i * 256];
        s += v[i];
        s2 += v[i] * v[i];
    }
    __shared__ float redA[8], redB[8];
#pragma unroll
    for (int o = 16; o; o >>= 1) {
        s += __shfl_xor_sync(~0u, s, o);
        s2 += __shfl_xor_sync(~0u, s2, o);
    }
    if ((t & 31) == 0) { redA[t >> 5] = s; redB[t >> 5] = s2; }
    __syncthreads();
    if (t < 32) {
        float a = (t < 8) ? redA[t] : 0.f;
        float c = (t < 8) ? redB[t] : 0.f;
#pragma unroll
        for (int o = 4; o; o >>= 1) {
            a += __shfl_xor_sync(~0u, a, o);
            c += __shfl_xor_sync(~0u, c, o);
        }
        if (t == 0) { redA[0] = a; redB[0] = c; }
    }
    __syncthreads();
    float mu = redA[0] * (1.0f / D);
    float var = redB[0] * (1.0f / D) - mu * mu;
    float rstd = rsqrtf(var + 1e-5f);
    float* xo = g_x + (size_t)row * D;
#pragma unroll
    for (int i = 0; i < 3; i++) {
        int c = t + i * 256;
        xo[c] = to_tf32((v[i] - mu) * rstd * gamma[c] + beta[c]);
    }
}

__global__ void __launch_bounds__(256) cvt_w(const float* __restrict__ Wq,
                                             const float* __restrict__ Wk,
                                             const float* __restrict__ Wv,
                                             const float* __restrict__ Wo) {
    int i = blockIdx.x * 256 + threadIdx.x;
    int z = blockIdx.y;
    const float* src = (z == 0) ? Wq : (z == 1) ? Wk : (z == 2) ? Wv : Wo;
    g_wt[(size_t)z * D * D + i] = to_tf32(src[i]);
}

__global__ void patch_kernel(const float* __restrict__ boxes,
                             const int* __restrict__ iszs) {
    int idx = blockIdx.x * 256 + threadIdx.x;
    if (idx >= ROWS) return;
    int b = idx >> 9;
    float w = (float)iszs[b * 4 + 0];
    float h = (float)iszs[b * 4 + 1];
    const float* bx = boxes + (size_t)idx * 4;
    float p0 = bx[0] * w, p1 = bx[1] * h, p2 = bx[2] * w, p3 = bx[3] * h;
    float spw = floorf(w / 11.0f);
    float sph = floorf(h / 11.0f);
    float cx = floorf((p0 + p2) * 0.5f);
    float cy = floorf((p1 + p3) * 0.5f);
    int px = 0, py = 0;
    bool fx = false, fy = false;
#pragma unroll
    for (int j = 0; j < 11; j++) {
        float jl = (float)j, jh = (float)(j + 1);
        float lo = jl * spw, hi = jh * spw;
        if (!fx && lo <= cx && cx <= hi) { px = j; fx = true; }
        float lo2 = jl * sph, hi2 = jh * sph;
        if (!fy && lo2 <= cy && cy <= hi2) { py = j; fy = true; }
    }
    g_px[idx] = px;
    g_py[idx] = py;
}

// ================ mma.sync tf32 GEMM: C[8192,768] = A @ W^T + bias ================
// BM=128, BN=256, BK=32. 8 warps (2x4), warp tile 64x64. 3-stage cp.async pipeline.
#define BM 128
#define BN 256
#define BK 32
#define PADK 36
#define AF (BM * PADK)                 // 4608 floats
#define BF (BN * PADK)                 // 9216 floats
#define SSTRIDE (AF + BF)              // 13824 floats per stage
#define SSB (SSTRIDE * 4)              // bytes per stage
#define NCHUNK (D / BK)                // 24
#define GEMM_SMEM (3 * SSB)            // 165888 bytes
#define GT 256

__global__ void __launch_bounds__(GT, 1)
gemm_mma(const float* __restrict__ Aglob,
         const float* __restrict__ b0v, float* __restrict__ o0,
         const float* __restrict__ b1v, float* __restrict__ o1,
         const float* __restrict__ b2v, float* __restrict__ o2,
         int wsel, int head_layout) {
    extern __shared__ float smf[];
    uint32_t smb = smem_u32(smf);
    int tid = threadIdx.x;
    int z = blockIdx.z;
    const float* Wm = g_wt + (size_t)(wsel + z) * D * D;
    const float* bias = (z == 0) ? b0v : (z == 1) ? b1v : b2v;
    float* outp = (z == 0) ? o0 : (z == 1) ? o1 : o2;

    int r0 = blockIdx.y * BM;
    int c0 = blockIdx.x * BN;

    int lane = tid & 31, wid = tid >> 5;
    int wm = wid >> 2, wn = wid & 3;       // 2 x 4
    int g = lane >> 2, t = lane & 3;

    float acc[4][8][4];
#pragma unroll
    for (int i = 0; i < 4; i++)
#pragma unroll
        for (int j = 0; j < 8; j++)
#pragma unroll
            for (int r = 0; r < 4; r++) acc[i][j][r] = 0.f;

#define STAGE_CHUNK(cc, sbase)                                                      \
    do {                                                                            \
        uint32_t ab = (sbase);                                                      \
        uint32_t bb = (sbase) + AF * 4;                                             \
        _Pragma("unroll")                                                           \
        for (int i = 0; i < 4; i++) {                                               \
            int f = tid + i * GT;                                                   \
            int row = f >> 3, seg = f & 7;                                          \
            CP_ASYNC16(ab + (uint32_t)(row * PADK + seg * 4) * 4,                   \
                       Aglob + (size_t)(r0 + row) * D + (cc) * BK + seg * 4);       \
        }                                                                           \
        _Pragma("unroll")                                                           \
        for (int i = 0; i < 8; i++) {                                               \
            int f = tid + i * GT;                                                   \
            int row = f >> 3, seg = f & 7;                                          \
            CP_ASYNC16(bb + (uint32_t)(row * PADK + seg * 4) * 4,                   \
                       Wm + (size_t)(c0 + row) * D + (cc) * BK + seg * 4);          \
        }                                                                           \
        CP_COMMIT();                                                                \
    } while (0)

    // prologue: stages 0 and 1
    STAGE_CHUNK(0, smb);
    STAGE_CHUNK(1, smb + SSB);

    const float* rs = smf;                 // read stage
    uint32_t ws = smb + 2u * SSB;          // write stage

    for (int c = 0; c < NCHUNK; ++c) {
        if (c + 1 < NCHUNK) { CP_WAIT(1); } else { CP_WAIT(0); }
        __syncthreads();
        if (c + 2 < NCHUNK) {
            STAGE_CHUNK(c + 2, ws);
            ws += SSB;
            if (ws == smb + 3u * SSB) ws = smb;
        }

        const float* As = rs;
        const float* Bs = rs + AF;
#pragma unroll
        for (int ks = 0; ks < 4; ++ks) {
            int k = ks * 8;
            uint32_t af[4][4], bf[8][2];
#pragma unroll
            for (int mt = 0; mt < 4; mt++) {
                int m = wm * 64 + mt * 16 + g;
                af[mt][0] = __float_as_uint(As[m * PADK + k + t]);
                af[mt][1] = __float_as_uint(As[(m + 8) * PADK + k + t]);
                af[mt][2] = __float_as_uint(As[m * PADK + k + t + 4]);
                af[mt][3] = __float_as_uint(As[(m + 8) * PADK + k + t + 4]);
            }
#pragma unroll
            for (int nt = 0; nt < 8; nt++) {
                int n = wn * 64 + nt * 8 + g;
                bf[nt][0] = __float_as_uint(Bs[n * PADK + k + t]);
                bf[nt][1] = __float_as_uint(Bs[n * PADK + k + t + 4]);
            }
#pragma unroll
            for (int mt = 0; mt < 4; mt++)
#pragma unroll
                for (int nt = 0; nt < 8; nt++)
                    mma8(acc[mt][nt], af[mt], bf[nt]);
        }
        rs += SSTRIDE;
        if (rs == smf + 3 * SSTRIDE) rs = smf;
    }

#pragma unroll
    for (int mt = 0; mt < 4; mt++) {
#pragma unroll
        for (int nt = 0; nt < 8; nt++) {
            int cg = c0 + wn * 64 + nt * 8 + 2 * t;
            float b0 = bias[cg], b1 = bias[cg + 1];
#pragma unroll
            for (int half = 0; half < 2; half++) {
                int rg = r0 + wm * 64 + mt * 16 + g + half * 8;
                float v0 = acc[mt][nt][half * 2 + 0] + b0;
                float v1 = acc[mt][nt][half * 2 + 1] + b1;
                float* dst;
                if (head_layout) {
                    int bb = rg >> 9, n = rg & 511;
                    int hh = cg >> 6, dk = cg & 63;
                    dst = outp + (((size_t)(bb * H + hh) * N + n) * DK) + dk;
                    *(float2*)dst = make_float2(to_tf32(v0), to_tf32(v1));
                } else {
                    dst = outp + (size_t)rg * D + cg;
                    *(float2*)dst = make_float2(v0, v1);
                }
            }
        }
    }
}

// ================ attention with mma.sync tf32 + fused distance bias ================
// 512 threads, 16 warps (4x4). CTA = one (b,h) x 64 q rows. 3-buffer K/V pipeline.
#define AT 512
#define PADA 68
#define PADS 516
#define KVF (64 * PADA)                       // floats per K/V buffer (4352)
#define QS_OFF 0
#define KB_OFF (64 * PADA)                    // first of 3 buffers
#define SC_OFF (4 * 64 * PADA)                // 17408
#define LUT_OFF (SC_OFF + 64 * PADS)          // 50432
#define PK_OFF  (LUT_OFF + 448)               // 50880
#define ATT_SMEM ((PK_OFF + 256) * 4)         // 204544 bytes

__device__ __forceinline__ void load_chunk64(uint32_t dst_base, const float* src) {
    int tid = threadIdx.x;
#pragma unroll
    for (int it = 0; it < 2; ++it) {
        int idx = tid + it * AT;
        int row = idx >> 4, seg = idx & 15;
        CP_ASYNC16(dst_base + (uint32_t)(row * PADA + seg * 4) * 4, src + idx * 4);
    }
}

__global__ void __launch_bounds__(AT, 1) attn_mma(const float* __restrict__ dist_emb,
                                                  float* __restrict__ att_out) {
    extern __shared__ float sm[];
    uint32_t smb = smem_u32(sm);
    float* Qs = sm + QS_OFF;
    float* Sc = sm + SC_OFF;
    float* lut = sm + LUT_OFF;
    unsigned short* pk = (unsigned short*)(sm + PK_OFF);

    int tid = threadIdx.x;
    int bh = blockIdx.y;
    int b = bh / H;
    int h = bh - b * H;
    int q0 = blockIdx.x * 64;

    const float* Qg = g_q + ((size_t)bh * N + q0) * DK;
    const float* Kg = g_k + (size_t)bh * N * DK;
    const float* Vg = g_v + (size_t)bh * N * DK;

    int lane = tid & 31, wid = tid >> 5;
    int wm = wid >> 2, wn = wid & 3;      // 4 x 4
    int g = lane >> 2, t = lane & 3;
    const float scale = 0.125f;

    uint32_t kb0 = smb + KB_OFF * 4;      // 3 consecutive buffers of KVF floats

    // prologue: Q + K0 (one group), K1 (second group)
    load_chunk64(smb + QS_OFF * 4, Qg);
    load_chunk64(kb0, Kg);
    CP_COMMIT();
    load_chunk64(kb0 + KVF * 4, Kg + 4096);
    CP_COMMIT();

    // distance-bias LUT (441 entries; 512 threads cover it) + packed patch coords
    if (tid < 441) {
        int dyc = tid / 21 - 10, dxc = tid % 21 - 10;
        int bin = (int)(sqrtf((float)(dxc * dxc + dyc * dyc)) * 2.0f);
        lut[tid] = dist_emb[bin * H + h];
    }
    pk[tid] = (unsigned short)(g_py[b * N + tid] * 21 + g_px[b * N + tid]);

    // ---------- phase 1: S = Q K^T * scale ----------
    {
        const float* rk = sm + KB_OFF;
        uint32_t wk = kb0 + 2u * KVF * 4;
        for (int kt = 0; kt < 8; ++kt) {
            if (kt + 1 < 8) { CP_WAIT(1); } else { CP_WAIT(0); }
            __syncthreads();
            if (kt + 2 < 8) {
                load_chunk64(wk, Kg + (kt + 2) * 4096);
                CP_COMMIT();
                wk += KVF * 4;
                if (wk == kb0 + 3u * KVF * 4) wk = kb0;
            }
            const float* Ks = rk;
            float acc[2][4];
#pragma unroll
            for (int j = 0; j < 2; j++)
#pragma unroll
                for (int r = 0; r < 4; r++) acc[j][r] = 0.f;
#pragma unroll
            for (int ks = 0; ks < 8; ++ks) {
                int k = ks * 8;
                uint32_t af[4], bf[2][2];
                {
                    int m = wm * 16 + g;
                    af[0] = __float_as_uint(Qs[m * PADA + k + t]);
                    af[1] = __float_as_uint(Qs[(m + 8) * PADA + k + t]);
                    af[2] = __float_as_uint(Qs[m * PADA + k + t + 4]);
                    af[3] = __float_as_uint(Qs[(m + 8) * PADA + k + t + 4]);
                }
#pragma unroll
                for (int nt = 0; nt < 2; nt++) {
                    int n = wn * 16 + nt * 8 + g;
                    bf[nt][0] = __float_as_uint(Ks[n * PADA + k + t]);
                    bf[nt][1] = __float_as_uint(Ks[n * PADA + k + t + 4]);
                }
#pragma unroll
                for (int nt = 0; nt < 2; nt++)
                    mma8(acc[nt], af, bf[nt]);
            }
#pragma unroll
            for (int nt = 0; nt < 2; nt++) {
                int row = wm * 16 + g;
                int col = kt * 64 + wn * 16 + nt * 8 + 2 * t;
                *(float2*)&Sc[row * PADS + col] =
                    make_float2(acc[nt][0] * scale, acc[nt][1] * scale);
                *(float2*)&Sc[(row + 8) * PADS + col] =
                    make_float2(acc[nt][2] * scale, acc[nt][3] * scale);
            }
            rk += KVF;
            if (rk == sm + KB_OFF + 3 * KVF) rk = sm + KB_OFF;
        }
    }
    __syncthreads();   // Sc complete; K buffers idle

    // prefetch V chunks 0,1 — cp.async flight overlaps the softmax below
    load_chunk64(kb0, Vg);
    CP_COMMIT();
    load_chunk64(kb0 + KVF * 4, Vg + 4096);
    CP_COMMIT();

    // ---------- phase 2: 2-pass softmax (scores bounded; no max subtraction) ----------
#pragma unroll
    for (int rr = 0; rr < 4; rr++) {
        int qi = wid * 4 + rr;
        int qg = q0 + qi;
        int coff = 220 - (int)pk[qg];
        float* srow = Sc + qi * PADS;
        float ssum = 0.f;
        for (int kk = lane; kk < N; kk += 32) {
            float e = __expf(srow[kk] + lut[(int)pk[kk] + coff]);
            srow[kk] = e;
            ssum += e;
        }
#pragma unroll
        for (int o = 16; o; o >>= 1) ssum += __shfl_xor_sync(~0u, ssum, o);
        float inv = 1.0f / ssum;
        float* arow = att_out + ((size_t)bh * N + qg) * N;
        for (int kk = lane; kk < N; kk += 32) {
            float p = srow[kk] * inv;
            arow[kk] = p;
            srow[kk] = to_tf32(p);
        }
    }

    // ---------- phase 3: O = P V ----------
    float oacc[2][4];
#pragma unroll
    for (int j = 0; j < 2; j++)
#pragma unroll
        for (int r = 0; r < 4; r++) oacc[j][r] = 0.f;

    {
        const float* rv = sm + KB_OFF;
        uint32_t wv = kb0 + 2u * KVF * 4;
        for (int kt = 0; kt < 8; ++kt) {
            if (kt + 1 < 8) { CP_WAIT(1); } else { CP_WAIT(0); }
            __syncthreads();   // kt=0: also orders phase-2 Sc writes before fragment reads
            if (kt + 2 < 8) {
                load_chunk64(wv, Vg + (kt + 2) * 4096);
                CP_COMMIT();
                wv += KVF * 4;
                if (wv == kb0 + 3u * KVF * 4) wv = kb0;
            }
            const float* Vs = rv;
#pragma unroll
            for (int ks = 0; ks < 8; ++ks) {
                int k = ks * 8;
                uint32_t af[4], bf[2][2];
                {
                    int m = wm * 16 + g;
                    int sb = m * PADS + kt * 64 + k;
                    af[0] = __float_as_uint(Sc[sb + t]);
                    af[1] = __float_as_uint(Sc[sb + 8 * PADS + t]);
                    af[2] = __float_as_uint(Sc[sb + t + 4]);
                    af[3] = __float_as_uint(Sc[sb + 8 * PADS + t + 4]);
                }
#pragma unroll
                for (int nt = 0; nt < 2; nt++) {
                    int n = wn * 16 + nt * 8 + g;
                    bf[nt][0] = __float_as_uint(Vs[(k + t) * PADA + n]);
                    bf[nt][1] = __float_as_uint(Vs[(k + t + 4) * PADA + n]);
                }
#pragma unroll
                for (int nt = 0; nt < 2; nt++)
                    mma8(oacc[nt], af, bf[nt]);
            }
            rv += KVF;
            if (rv == sm + KB_OFF + 3 * KVF) rv = sm + KB_OFF;
        }
    }

#pragma unroll
    for (int nt = 0; nt < 2; nt++) {
        int dk = wn * 16 + nt * 8 + 2 * t;
#pragma unroll
        for (int half = 0; half < 2; half++) {
            int qg = q0 + wm * 16 + g + half * 8;
            float* dst = g_ao + ((size_t)(b * N + qg)) * D + h * DK + dk;
            *(float2*)dst = make_float2(to_tf32(oacc[nt][half * 2 + 0]),
                                        to_tf32(oacc[nt][half * 2 + 1]));
        }
    }
}

// ---------------- launch ----------------
extern "C" void kernel_launch(void* const* d_in, const int* in_sizes, int n_in,
                              void* d_out, int out_size) {
    const float* features = (const float*)d_in[0];
    const float* boxes    = (const float*)d_in[1];
    const int*   iszs     = (const int*)  d_in[2];
    const float* Wq = (const float*)d_in[3];
    const float* bq = (const float*)d_in[4];
    const float* Wk = (const float*)d_in[5];
    const float* bk = (const float*)d_in[6];
    const float* Wv = (const float*)d_in[7];
    const float* bv = (const float*)d_in[8];
    const float* Wo = (const float*)d_in[9];
    const float* bo = (const float*)d_in[10];
    const float* gamma = (const float*)d_in[11];
    const float* beta  = (const float*)d_in[12];
    const float* dist_emb = (const float*)d_in[13];

    float* out = (float*)d_out;
    float* att = ((size_t)out_size >= OUT_ELEMS + ATT_ELEMS) ? out + OUT_ELEMS : out;

    cudaFuncSetAttribute(attn_mma, cudaFuncAttributeMaxDynamicSharedMemorySize, ATT_SMEM);
    cudaFuncSetAttribute(gemm_mma, cudaFuncAttributeMaxDynamicSharedMemorySize, GEMM_SMEM);

    float *gx, *gq, *gk, *gv, *gao;
    cudaGetSymbolAddress((void**)&gx, g_x);
    cudaGetSymbolAddress((void**)&gq, g_q);
    cudaGetSymbolAddress((void**)&gk, g_k);
    cudaGetSymbolAddress((void**)&gv, g_v);
    cudaGetSymbolAddress((void**)&gao, g_ao);

    ln_kernel<<<ROWS, 256>>>(features, gamma, beta);
    cvt_w<<<dim3((D * D) / 256, 4), 256>>>(Wq, Wk, Wv, Wo);
    patch_kernel<<<(ROWS + 255) / 256, 256>>>(boxes, iszs);

    dim3 gq3(D / BN, ROWS / BM, 3);
    gemm_mma<<<gq3, GT, GEMM_SMEM>>>(gx, bq, gq, bk, gk, bv, gv, 0, 1);

    dim3 ga(N / 64, B * H);
    attn_mma<<<ga, AT, ATT_SMEM>>>(dist_emb, att);

    dim3 go3(D / BN, ROWS / BM, 1);
    gemm_mma<<<go3, GT, GEMM_SMEM>>>(gao, bo, out, bo, out, bo, out, 3, 0);
}

// round 12
// speedup vs baseline: 1.0680x; 1.0301x over previous
#include <cuda_runtime.h>
#include <math.h>
#include <stdint.h>

#define B 16
#define N 512
#define D 768
#define H 12
#define DK 64
#define ND 32
#define ROWS (B * N)
#define OUT_ELEMS ((size_t)B * N * D)
#define ATT_ELEMS ((size_t)B * H * N * N)

// ---------------- scratch ----------------
__device__ float g_x[ROWS * D];
__device__ float g_q[ROWS * D];
__device__ float g_k[ROWS * D];
__device__ float g_v[ROWS * D];
__device__ float g_ao[ROWS * D];
__device__ float g_wt[4 * D * D];
__device__ int g_px[ROWS];
__device__ int g_py[ROWS];

__device__ __forceinline__ float to_tf32(float x) {
    uint32_t u;
    asm("cvt.rna.tf32.f32 %0, %1;" : "=r"(u) : "f"(x));
    return __uint_as_float(u);
}
__device__ __forceinline__ uint32_t smem_u32(const void* p) {
    uint32_t a;
    asm("{ .reg .u64 t; cvta.to.shared.u64 t, %1; cvt.u32.u64 %0, t; }" : "=r"(a) : "l"(p));
    return a;
}
#define CP_ASYNC16(dst, src) asm volatile("cp.async.cg.shared.global [%0], [%1], 16;" :: "r"(dst), "l"(src) : "memory")
#define CP_COMMIT()          asm volatile("cp.async.commit_group;" ::: "memory")
#define CP_WAIT(nn)          asm volatile("cp.async.wait_group %0;" :: "n"(nn) : "memory")

__device__ __forceinline__ void mma8(float* d, const uint32_t* a, const uint32_t* b) {
    asm volatile("mma.sync.aligned.m16n8k8.row.col.f32.tf32.tf32.f32 "
                 "{%0,%1,%2,%3}, {%4,%5,%6,%7}, {%8,%9}, {%0,%1,%2,%3};"
                 : "+f"(d[0]), "+f"(d[1]), "+f"(d[2]), "+f"(d[3])
                 : "r"(a[0]), "r"(a[1]), "r"(a[2]), "r"(a[3]), "r"(b[0]), "r"(b[1]));
}

// ---------------- LayerNorm (writes tf32-rounded) ----------------
__global__ void __launch_bounds__(256) ln_kernel(const float* __restrict__ f,
                                                 const float* __restrict__ gamma,
                                                 const float* __restrict__ beta) {
    int row = blockIdx.x;
    int t = threadIdx.x;
    const float* x = f + (size_t)row * D;
    float v[3];
    float s = 0.f, s2 = 0.f;
#pragma unroll
    for (int i = 0; i < 3; i++) {
        v[i] = x[t + i * 256];
        s += v[i];
        s2 += v[i] * v[i];
    }
    __shared__ float redA[8], redB[8];
#pragma unroll
    for (int o = 16; o; o >>= 1) {
        s += __shfl_xor_sync(~0u, s, o);
        s2 += __shfl_xor_sync(~0u, s2, o);
    }
    if ((t & 31) == 0) { redA[t >> 5] = s; redB[t >> 5] = s2; }
    __syncthreads();
    if (t < 32) {
        float a = (t < 8) ? redA[t] : 0.f;
        float c = (t < 8) ? redB[t] : 0.f;
#pragma unroll
        for (int o = 4; o; o >>= 1) {
            a += __shfl_xor_sync(~0u, a, o);
            c += __shfl_xor_sync(~0u, c, o);
        }
        if (t == 0) { redA[0] = a; redB[0] = c; }
    }
    __syncthreads();
    float mu = redA[0] * (1.0f / D);
    float var = redB[0] * (1.0f / D) - mu * mu;
    float rstd = rsqrtf(var + 1e-5f);
    float* xo = g_x + (size_t)row * D;
#pragma unroll
    for (int i = 0; i < 3; i++) {
        int c = t + i * 256;
        xo[c] = to_tf32((v[i] - mu) * rstd * gamma[c] + beta[c]);
    }
}

__global__ void __launch_bounds__(256) cvt_w(const float* __restrict__ Wq,
                                             const float* __restrict__ Wk,
                                             const float* __restrict__ Wv,
                                             const float* __restrict__ Wo) {
    int i = blockIdx.x * 256 + threadIdx.x;
    int z = blockIdx.y;
    const float* src = (z == 0) ? Wq : (z == 1) ? Wk : (z == 2) ? Wv : Wo;
    g_wt[(size_t)z * D * D + i] = to_tf32(src[i]);
}

__global__ void patch_kernel(const float* __restrict__ boxes,
                             const int* __restrict__ iszs) {
    int idx = blockIdx.x * 256 + threadIdx.x;
    if (idx >= ROWS) return;
    int b = idx >> 9;
    float w = (float)iszs[b * 4 + 0];
    float h = (float)iszs[b * 4 + 1];
    const float* bx = boxes + (size_t)idx * 4;
    float p0 = bx[0] * w, p1 = bx[1] * h, p2 = bx[2] * w, p3 = bx[3] * h;
    float spw = floorf(w / 11.0f);
    float sph = floorf(h / 11.0f);
    float cx = floorf((p0 + p2) * 0.5f);
    float cy = floorf((p1 + p3) * 0.5f);
    int px = 0, py = 0;
    bool fx = false, fy = false;
#pragma unroll
    for (int j = 0; j < 11; j++) {
        float jl = (float)j, jh = (float)(j + 1);
        float lo = jl * spw, hi = jh * spw;
        if (!fx && lo <= cx && cx <= hi) { px = j; fx = true; }
        float lo2 = jl * sph, hi2 = jh * sph;
        if (!fy && lo2 <= cy && cy <= hi2) { py = j; fy = true; }
    }
    g_px[idx] = px;
    g_py[idx] = py;
}

// ================ mma.sync tf32 GEMM: C[8192,768] = A @ W^T + bias ================
// BM=128, BN=256, BK=32. 8 warps (2x4), warp tile 64x64. 3-stage cp.async pipeline.
#define BM 128
#define BN 256
#define BK 32
#define PADK 36
#define AF (BM * PADK)                 // 4608 floats
#define BF (BN * PADK)                 // 9216 floats
#define SSTRIDE (AF + BF)              // 13824 floats per stage
#define SSB (SSTRIDE * 4)              // bytes per stage
#define NCHUNK (D / BK)                // 24
#define GEMM_SMEM (3 * SSB)            // 165888 bytes
#define GT 256

__global__ void __launch_bounds__(GT, 1)
gemm_mma(const float* __restrict__ Aglob,
         const float* __restrict__ b0v, float* __restrict__ o0,
         const float* __restrict__ b1v, float* __restrict__ o1,
         const float* __restrict__ b2v, float* __restrict__ o2,
         int wsel, int head_layout) {
    extern __shared__ float smf[];
    uint32_t smb = smem_u32(smf);
    int tid = threadIdx.x;
    int z = blockIdx.z;
    const float* Wm = g_wt + (size_t)(wsel + z) * D * D;
    const float* bias = (z == 0) ? b0v : (z == 1) ? b1v : b2v;
    float* outp = (z == 0) ? o0 : (z == 1) ? o1 : o2;

    int r0 = blockIdx.y * BM;
    int c0 = blockIdx.x * BN;

    int lane = tid & 31, wid = tid >> 5;
    int wm = wid >> 2, wn = wid & 3;       // 2 x 4
    int g = lane >> 2, t = lane & 3;

    float acc[4][8][4];
#pragma unroll
    for (int i = 0; i < 4; i++)
#pragma unroll
        for (int j = 0; j < 8; j++)
#pragma unroll
            for (int r = 0; r < 4; r++) acc[i][j][r] = 0.f;

#define STAGE_CHUNK(cc, sbase)                                                      \
    do {                                                                            \
        uint32_t ab = (sbase);                                                      \
        uint32_t bb = (sbase) + AF * 4;                                             \
        _Pragma("unroll")                                                           \
        for (int i = 0; i < 4; i++) {                                               \
            int f = tid + i * GT;                                                   \
            int row = f >> 3, seg = f & 7;                                          \
            CP_ASYNC16(ab + (uint32_t)(row * PADK + seg * 4) * 4,                   \
                       Aglob + (size_t)(r0 + row) * D + (cc) * BK + seg * 4);       \
        }                                                                           \
        _Pragma("unroll")                                                           \
        for (int i = 0; i < 8; i++) {                                               \
            int f = tid + i * GT;                                                   \
            int row = f >> 3, seg = f & 7;                                          \
            CP_ASYNC16(bb + (uint32_t)(row * PADK + seg * 4) * 4,                   \
                       Wm + (size_t)(c0 + row) * D + (cc) * BK + seg * 4);          \
        }                                                                           \
        CP_COMMIT();                                                                \
    } while (0)

    // prologue: stages 0 and 1
    STAGE_CHUNK(0, smb);
    STAGE_CHUNK(1, smb + SSB);

    const float* rs = smf;                 // read stage
    uint32_t ws = smb + 2u * SSB;          // write stage

    for (int c = 0; c < NCHUNK; ++c) {
        if (c + 1 < NCHUNK) { CP_WAIT(1); } else { CP_WAIT(0); }
        __syncthreads();
        if (c + 2 < NCHUNK) {
            STAGE_CHUNK(c + 2, ws);
            ws += SSB;
            if (ws == smb + 3u * SSB) ws = smb;
        }

        const float* As = rs;
        const float* Bs = rs + AF;
#pragma unroll
        for (int ks = 0; ks < 4; ++ks) {
            int k = ks * 8;
            uint32_t af[4][4], bf[8][2];
#pragma unroll
            for (int mt = 0; mt < 4; mt++) {
                int m = wm * 64 + mt * 16 + g;
                af[mt][0] = __float_as_uint(As[m * PADK + k + t]);
                af[mt][1] = __float_as_uint(As[(m + 8) * PADK + k + t]);
                af[mt][2] = __float_as_uint(As[m * PADK + k + t + 4]);
                af[mt][3] = __float_as_uint(As[(m + 8) * PADK + k + t + 4]);
            }
#pragma unroll
            for (int nt = 0; nt < 8; nt++) {
                int n = wn * 64 + nt * 8 + g;
                bf[nt][0] = __float_as_uint(Bs[n * PADK + k + t]);
                bf[nt][1] = __float_as_uint(Bs[n * PADK + k + t + 4]);
            }
#pragma unroll
            for (int mt = 0; mt < 4; mt++)
#pragma unroll
                for (int nt = 0; nt < 8; nt++)
                    mma8(acc[mt][nt], af[mt], bf[nt]);
        }
        rs += SSTRIDE;
        if (rs == smf + 3 * SSTRIDE) rs = smf;
    }

#pragma unroll
    for (int mt = 0; mt < 4; mt++) {
#pragma unroll
        for (int nt = 0; nt < 8; nt++) {
            int cg = c0 + wn * 64 + nt * 8 + 2 * t;
            float b0 = bias[cg], b1 = bias[cg + 1];
#pragma unroll
            for (int half = 0; half < 2; half++) {
                int rg = r0 + wm * 64 + mt * 16 + g + half * 8;
                float v0 = acc[mt][nt][half * 2 + 0] + b0;
                float v1 = acc[mt][nt][half * 2 + 1] + b1;
                float* dst;
                if (head_layout) {
                    int bb = rg >> 9, n = rg & 511;
                    int hh = cg >> 6, dk = cg & 63;
                    dst = outp + (((size_t)(bb * H + hh) * N + n) * DK) + dk;
                    *(float2*)dst = make_float2(to_tf32(v0), to_tf32(v1));
                } else {
                    dst = outp + (size_t)rg * D + cg;
                    *(float2*)dst = make_float2(v0, v1);
                }
            }
        }
    }
}

// ================ attention with mma.sync tf32 + fused distance bias ================
// 512 threads, 16 warps (4x4). CTA = one (b,h) x 64 q rows. 3-buffer K/V pipeline.
#define AT 512
#define PADA 68
#define PADS 516
#define KVF (64 * PADA)                       // floats per K/V buffer (4352)
#define QS_OFF 0
#define KB_OFF (64 * PADA)                    // first of 3 buffers
#define SC_OFF (4 * 64 * PADA)                // 17408
#define LUT_OFF (SC_OFF + 64 * PADS)          // 50432
#define PK_OFF  (LUT_OFF + 448)               // 50880
#define ATT_SMEM ((PK_OFF + 256) * 4)         // 204544 bytes

__device__ __forceinline__ void load_chunk64(uint32_t dst_base, const float* src) {
    int tid = threadIdx.x;
#pragma unroll
    for (int it = 0; it < 2; ++it) {
        int idx = tid + it * AT;
        int row = idx >> 4, seg = idx & 15;
        CP_ASYNC16(dst_base + (uint32_t)(row * PADA + seg * 4) * 4, src + idx * 4);
    }
}

__global__ void __launch_bounds__(AT, 1) attn_mma(const float* __restrict__ dist_emb,
                                                  float* __restrict__ att_out) {
    extern __shared__ float sm[];
    uint32_t smb = smem_u32(sm);
    float* Qs = sm + QS_OFF;
    float* Sc = sm + SC_OFF;
    float* lut = sm + LUT_OFF;
    unsigned short* pk = (unsigned short*)(sm + PK_OFF);

    int tid = threadIdx.x;
    int bh = blockIdx.y;
    int b = bh / H;
    int h = bh - b * H;
    int q0 = blockIdx.x * 64;

    const float* Qg = g_q + ((size_t)bh * N + q0) * DK;
    const float* Kg = g_k + (size_t)bh * N * DK;
    const float* Vg = g_v + (size_t)bh * N * DK;

    int lane = tid & 31, wid = tid >> 5;
    int wm = wid >> 2, wn = wid & 3;      // 4 x 4
    int g = lane >> 2, t = lane & 3;
    const float scale = 0.125f;

    uint32_t kb0 = smb + KB_OFF * 4;      // 3 consecutive buffers of KVF floats

    // prologue: Q + K0 (one group), K1 (second group)
    load_chunk64(smb + QS_OFF * 4, Qg);
    load_chunk64(kb0, Kg);
    CP_COMMIT();
    load_chunk64(kb0 + KVF * 4, Kg + 4096);
    CP_COMMIT();

    // distance-bias LUT (441 entries) + packed patch coords
    if (tid < 441) {
        int dyc = tid / 21 - 10, dxc = tid % 21 - 10;
        int bin = (int)(sqrtf((float)(dxc * dxc + dyc * dyc)) * 2.0f);
        lut[tid] = dist_emb[bin * H + h];
    }
    pk[tid] = (unsigned short)(g_py[b * N + tid] * 21 + g_px[b * N + tid]);

    // ---------- phase 1: S = Q K^T * scale ----------
    {
        const float* rk = sm + KB_OFF;
        uint32_t wk = kb0 + 2u * KVF * 4;
        for (int kt = 0; kt < 8; ++kt) {
            if (kt + 1 < 8) { CP_WAIT(1); } else { CP_WAIT(0); }
            __syncthreads();
            if (kt + 2 < 8) {
                load_chunk64(wk, Kg + (kt + 2) * 4096);
                CP_COMMIT();
                wk += KVF * 4;
                if (wk == kb0 + 3u * KVF * 4) wk = kb0;
            }
            const float* Ks = rk;
            float acc[2][4];
#pragma unroll
            for (int j = 0; j < 2; j++)
#pragma unroll
                for (int r = 0; r < 4; r++) acc[j][r] = 0.f;
#pragma unroll
            for (int ks = 0; ks < 8; ++ks) {
                int k = ks * 8;
                uint32_t af[4], bf[2][2];
                {
                    int m = wm * 16 + g;
                    af[0] = __float_as_uint(Qs[m * PADA + k + t]);
                    af[1] = __float_as_uint(Qs[(m + 8) * PADA + k + t]);
                    af[2] = __float_as_uint(Qs[m * PADA + k + t + 4]);
                    af[3] = __float_as_uint(Qs[(m + 8) * PADA + k + t + 4]);
                }
#pragma unroll
                for (int nt = 0; nt < 2; nt++) {
                    int n = wn * 16 + nt * 8 + g;
                    bf[nt][0] = __float_as_uint(Ks[n * PADA + k + t]);
                    bf[nt][1] = __float_as_uint(Ks[n * PADA + k + t + 4]);
                }
#pragma unroll
                for (int nt = 0; nt < 2; nt++)
                    mma8(acc[nt], af, bf[nt]);
            }
#pragma unroll
            for (int nt = 0; nt < 2; nt++) {
                int row = wm * 16 + g;
                int col = kt * 64 + wn * 16 + nt * 8 + 2 * t;
                *(float2*)&Sc[row * PADS + col] =
                    make_float2(acc[nt][0] * scale, acc[nt][1] * scale);
                *(float2*)&Sc[(row + 8) * PADS + col] =
                    make_float2(acc[nt][2] * scale, acc[nt][3] * scale);
            }
            rk += KVF;
            if (rk == sm + KB_OFF + 3 * KVF) rk = sm + KB_OFF;
        }
    }
    __syncthreads();   // Sc complete; K buffers idle

    // prefetch V chunks 0,1 — cp.async flight overlaps the softmax below
    load_chunk64(kb0, Vg);
    CP_COMMIT();
    load_chunk64(kb0 + KVF * 4, Vg + 4096);
    CP_COMMIT();

    // ---------- phase 2: 2-pass softmax, float4-vectorized ----------
#pragma unroll
    for (int rr = 0; rr < 4; rr++) {
        int qi = wid * 4 + rr;
        int qg = q0 + qi;
        int coff = 220 - (int)pk[qg];
        float* srow = Sc + qi * PADS;
        float ssum = 0.f;
#pragma unroll
        for (int i = 0; i < 4; i++) {
            int kk = lane * 4 + 128 * i;
            float4 s4 = *(const float4*)&srow[kk];
            ushort4 p4 = *(const ushort4*)&pk[kk];
            float e0 = __expf(s4.x + lut[(int)p4.x + coff]);
            float e1 = __expf(s4.y + lut[(int)p4.y + coff]);
            float e2 = __expf(s4.z + lut[(int)p4.z + coff]);
            float e3 = __expf(s4.w + lut[(int)p4.w + coff]);
            *(float4*)&srow[kk] = make_float4(e0, e1, e2, e3);
            ssum += (e0 + e1) + (e2 + e3);
        }
#pragma unroll
        for (int o = 16; o; o >>= 1) ssum += __shfl_xor_sync(~0u, ssum, o);
        float inv = 1.0f / ssum;
        float* arow = att_out + ((size_t)bh * N + qg) * N;
#pragma unroll
        for (int i = 0; i < 4; i++) {
            int kk = lane * 4 + 128 * i;
            float4 e4 = *(const float4*)&srow[kk];
            float4 p4 = make_float4(e4.x * inv, e4.y * inv, e4.z * inv, e4.w * inv);
            *(float4*)&arow[kk] = p4;
            *(float4*)&srow[kk] = make_float4(to_tf32(p4.x), to_tf32(p4.y),
                                              to_tf32(p4.z), to_tf32(p4.w));
        }
    }

    // ---------- phase 3: O = P V ----------
    float oacc[2][4];
#pragma unroll
    for (int j = 0; j < 2; j++)
#pragma unroll
        for (int r = 0; r < 4; r++) oacc[j][r] = 0.f;

    {
        const float* rv = sm + KB_OFF;
        uint32_t wv = kb0 + 2u * KVF * 4;
        for (int kt = 0; kt < 8; ++kt) {
            if (kt + 1 < 8) { CP_WAIT(1); } else { CP_WAIT(0); }
            __syncthreads();   // kt=0: also orders phase-2 Sc writes before fragment reads
            if (kt + 2 < 8) {
                load_chunk64(wv, Vg + (kt + 2) * 4096);
                CP_COMMIT();
                wv += KVF * 4;
                if (wv == kb0 + 3u * KVF * 4) wv = kb0;
            }
            const float* Vs = rv;
#pragma unroll
            for (int ks = 0; ks < 8; ++ks) {
                int k = ks * 8;
                uint32_t af[4], bf[2][2];
                {
                    int m = wm * 16 + g;
                    int sb = m * PADS + kt * 64 + k;
                    af[0] = __float_as_uint(Sc[sb + t]);
                    af[1] = __float_as_uint(Sc[sb + 8 * PADS + t]);
                    af[2] = __float_as_uint(Sc[sb + t + 4]);
                    af[3] = __float_as_uint(Sc[sb + 8 * PADS + t + 4]);
                }
#pragma unroll
                for (int nt = 0; nt < 2; nt++) {
                    int n = wn * 16 + nt * 8 + g;
                    bf[nt][0] = __float_as_uint(Vs[(k + t) * PADA + n]);
                    bf[nt][1] = __float_as_uint(Vs[(k + t + 4) * PADA + n]);
                }
#pragma unroll
                for (int nt = 0; nt < 2; nt++)
                    mma8(oacc[nt], af, bf[nt]);
            }
            rv += KVF;
            if (rv == sm + KB_OFF + 3 * KVF) rv = sm + KB_OFF;
        }
    }

#pragma unroll
    for (int nt = 0; nt < 2; nt++) {
        int dk = wn * 16 + nt * 8 + 2 * t;
#pragma unroll
        for (int half = 0; half < 2; half++) {
            int qg = q0 + wm * 16 + g + half * 8;
            float* dst = g_ao + ((size_t)(b * N + qg)) * D + h * DK + dk;
            *(float2*)dst = make_float2(to_tf32(oacc[nt][half * 2 + 0]),
                                        to_tf32(oacc[nt][half * 2 + 1]));
        }
    }
}

// ---------------- launch ----------------
extern "C" void kernel_launch(void* const* d_in, const int* in_sizes, int n_in,
                              void* d_out, int out_size) {
    const float* features = (const float*)d_in[0];
    const float* boxes    = (const float*)d_in[1];
    const int*   iszs     = (const int*)  d_in[2];
    const float* Wq = (const float*)d_in[3];
    const float* bq = (const float*)d_in[4];
    const float* Wk = (const float*)d_in[5];
    const float* bk = (const float*)d_in[6];
    const float* Wv = (const float*)d_in[7];
    const float* bv = (const float*)d_in[8];
    const float* Wo = (const float*)d_in[9];
    const float* bo = (const float*)d_in[10];
    const float* gamma = (const float*)d_in[11];
    const float* beta  = (const float*)d_in[12];
    const float* dist_emb = (const float*)d_in[13];

    float* out = (float*)d_out;
    float* att = ((size_t)out_size >= OUT_ELEMS + ATT_ELEMS) ? out + OUT_ELEMS : out;

    cudaFuncSetAttribute(attn_mma, cudaFuncAttributeMaxDynamicSharedMemorySize, ATT_SMEM);
    cudaFuncSetAttribute(gemm_mma, cudaFuncAttributeMaxDynamicSharedMemorySize, GEMM_SMEM);

    float *gx, *gq, *gk, *gv, *gao;
    cudaGetSymbolAddress((void**)&gx, g_x);
    cudaGetSymbolAddress((void**)&gq, g_q);
    cudaGetSymbolAddress((void**)&gk, g_k);
    cudaGetSymbolAddress((void**)&gv, g_v);
    cudaGetSymbolAddress((void**)&gao, g_ao);

    ln_kernel<<<ROWS, 256>>>(features, gamma, beta);
    cvt_w<<<dim3((D * D) / 256, 4), 256>>>(Wq, Wk, Wv, Wo);
    patch_kernel<<<(ROWS + 255) / 256, 256>>>(boxes, iszs);

    dim3 gq3(D / BN, ROWS / BM, 3);
    gemm_mma<<<gq3, GT, GEMM_SMEM>>>(gx, bq, gq, bk, gk, bv, gv, 0, 1);

    dim3 ga(N / 64, B * H);
    attn_mma<<<ga, AT, ATT_SMEM>>>(dist_emb, att);

    dim3 go3(D / BN, ROWS / BM, 1);
    gemm_mma<<<go3, GT, GEMM_SMEM>>>(gao, bo, out, bo, out, bo, out, 3, 0);
}

// round 13
// speedup vs baseline: 1.1595x; 1.0857x over previous
#include <cuda_runtime.h>
#include <math.h>
#include <stdint.h>

#define B 16
#define N 512
#define D 768
#define H 12
#define DK 64
#define ND 32
#define ROWS (B * N)
#define OUT_ELEMS ((size_t)B * N * D)
#define ATT_ELEMS ((size_t)B * H * N * N)

// ---------------- scratch ----------------
__device__ float g_x[ROWS * D];
__device__ float g_q[ROWS * D];
__device__ float g_k[ROWS * D];
__device__ float g_v[ROWS * D];
__device__ float g_ao[ROWS * D];
__device__ float g_wt[4 * D * D];
__device__ int g_px[ROWS];
__device__ int g_py[ROWS];

__device__ __forceinline__ float to_tf32(float x) {
    uint32_t u;
    asm("cvt.rna.tf32.f32 %0, %1;" : "=r"(u) : "f"(x));
    return __uint_as_float(u);
}
// within-8 column permutation: k -> 2*(k&3) + (k>>2); maps (t, t+4) -> (2t, 2t+1)
__device__ __forceinline__ int perm3(int x) { return ((x & 3) << 1) | (x >> 2); }

__device__ __forceinline__ uint32_t smem_u32(const void* p) {
    uint32_t a;
    asm("{ .reg .u64 t; cvta.to.shared.u64 t, %1; cvt.u32.u64 %0, t; }" : "=r"(a) : "l"(p));
    return a;
}
#define CP_ASYNC16(dst, src) asm volatile("cp.async.cg.shared.global [%0], [%1], 16;" :: "r"(dst), "l"(src) : "memory")
#define CP_COMMIT()          asm volatile("cp.async.commit_group;" ::: "memory")
#define CP_WAIT(nn)          asm volatile("cp.async.wait_group %0;" :: "n"(nn) : "memory")

__device__ __forceinline__ void mma8(float* d, const uint32_t* a, const uint32_t* b) {
    asm volatile("mma.sync.aligned.m16n8k8.row.col.f32.tf32.tf32.f32 "
                 "{%0,%1,%2,%3}, {%4,%5,%6,%7}, {%8,%9}, {%0,%1,%2,%3};"
                 : "+f"(d[0]), "+f"(d[1]), "+f"(d[2]), "+f"(d[3])
                 : "r"(a[0]), "r"(a[1]), "r"(a[2]), "r"(a[3]), "r"(b[0]), "r"(b[1]));
}

// ---------------- LayerNorm (writes tf32-rounded, column-permuted) ----------------
__global__ void __launch_bounds__(256) ln_kernel(const float* __restrict__ f,
                                                 const float* __restrict__ gamma,
                                                 const float* __restrict__ beta) {
    int row = blockIdx.x;
    int t = threadIdx.x;
    const float* x = f + (size_t)row * D;
    float v[3];
    float s = 0.f, s2 = 0.f;
#pragma unroll
    for (int i = 0; i < 3; i++) {
        v[i] = x[t + i * 256];
        s += v[i];
        s2 += v[i] * v[i];
    }
    __shared__ float redA[8], redB[8];
#pragma unroll
    for (int o = 16; o; o >>= 1) {
        s += __shfl_xor_sync(~0u, s, o);
        s2 += __shfl_xor_sync(~0u, s2, o);
    }
    if ((t & 31) == 0) { redA[t >> 5] = s; redB[t >> 5] = s2; }
    __syncthreads();
    if (t < 32) {
        float a = (t < 8) ? redA[t] : 0.f;
        float c = (t < 8) ? redB[t] : 0.f;
#pragma unroll
        for (int o = 4; o; o >>= 1) {
            a += __shfl_xor_sync(~0u, a, o);
            c += __shfl_xor_sync(~0u, c, o);
        }
        if (t == 0) { redA[0] = a; redB[0] = c; }
    }
    __syncthreads();
    float mu = redA[0] * (1.0f / D);
    float var = redB[0] * (1.0f / D) - mu * mu;
    float rstd = rsqrtf(var + 1e-5f);
    float* xo = g_x + (size_t)row * D;
#pragma unroll
    for (int i = 0; i < 3; i++) {
        int c = t + i * 256;
        int cp = (c & ~7) | perm3(c & 7);
        xo[cp] = to_tf32((v[i] - mu) * rstd * gamma[c] + beta[c]);
    }
}

// weights: tf32-round + permute K columns (row stride D is multiple of 8)
__global__ void __launch_bounds__(256) cvt_w(const float* __restrict__ Wq,
                                             const float* __restrict__ Wk,
                                             const float* __restrict__ Wv,
                                             const float* __restrict__ Wo) {
    int i = blockIdx.x * 256 + threadIdx.x;
    int z = blockIdx.y;
    const float* src = (z == 0) ? Wq : (z == 1) ? Wk : (z == 2) ? Wv : Wo;
    int ip = (i & ~7) | perm3(i & 7);
    g_wt[(size_t)z * D * D + ip] = to_tf32(src[i]);
}

__global__ void patch_kernel(const float* __restrict__ boxes,
                             const int* __restrict__ iszs) {
    int idx = blockIdx.x * 256 + threadIdx.x;
    if (idx >= ROWS) return;
    int b = idx >> 9;
    float w = (float)iszs[b * 4 + 0];
    float h = (float)iszs[b * 4 + 1];
    const float* bx = boxes + (size_t)idx * 4;
    float p0 = bx[0] * w, p1 = bx[1] * h, p2 = bx[2] * w, p3 = bx[3] * h;
    float spw = floorf(w / 11.0f);
    float sph = floorf(h / 11.0f);
    float cx = floorf((p0 + p2) * 0.5f);
    float cy = floorf((p1 + p3) * 0.5f);
    int px = 0, py = 0;
    bool fx = false, fy = false;
#pragma unroll
    for (int j = 0; j < 11; j++) {
        float jl = (float)j, jh = (float)(j + 1);
        float lo = jl * spw, hi = jh * spw;
        if (!fx && lo <= cx && cx <= hi) { px = j; fx = true; }
        float lo2 = jl * sph, hi2 = jh * sph;
        if (!fy && lo2 <= cy && cy <= hi2) { py = j; fy = true; }
    }
    g_px[idx] = px;
    g_py[idx] = py;
}

// ================ mma.sync tf32 GEMM: C[8192,768] = A @ W^T + bias ================
// BM=128, BN=256, BK=32. 8 warps (2x4), warp tile 64x64. 3-stage cp.async pipeline.
// Operands stored column-permuted (perm3) -> fragment loads are LDS.64.
#define BM 128
#define BN 256
#define BK 32
#define PADK 40
#define AF (BM * PADK)                 // 5120 floats
#define BF (BN * PADK)                 // 10240 floats
#define SSTRIDE (AF + BF)              // 15360 floats per stage
#define SSB (SSTRIDE * 4)              // 61440 bytes
#define NCHUNK (D / BK)                // 24
#define GEMM_SMEM (3 * SSB)            // 184320 bytes
#define GT 256

__global__ void __launch_bounds__(GT, 1)
gemm_mma(const float* __restrict__ Aglob,
         const float* __restrict__ b0v, float* __restrict__ o0,
         const float* __restrict__ b1v, float* __restrict__ o1,
         const float* __restrict__ b2v, float* __restrict__ o2,
         int wsel, int head_layout) {
    extern __shared__ float smf[];
    uint32_t smb = smem_u32(smf);
    int tid = threadIdx.x;
    int z = blockIdx.z;
    const float* Wm = g_wt + (size_t)(wsel + z) * D * D;
    const float* bias = (z == 0) ? b0v : (z == 1) ? b1v : b2v;
    float* outp = (z == 0) ? o0 : (z == 1) ? o1 : o2;

    int r0 = blockIdx.y * BM;
    int c0 = blockIdx.x * BN;

    int lane = tid & 31, wid = tid >> 5;
    int wm = wid >> 2, wn = wid & 3;       // 2 x 4
    int g = lane >> 2, t = lane & 3;

    float acc[4][8][4];
#pragma unroll
    for (int i = 0; i < 4; i++)
#pragma unroll
        for (int j = 0; j < 8; j++)
#pragma unroll
            for (int r = 0; r < 4; r++) acc[i][j][r] = 0.f;

#define STAGE_CHUNK(cc, sbase)                                                      \
    do {                                                                            \
        uint32_t ab = (sbase);                                                      \
        uint32_t bb = (sbase) + AF * 4;                                             \
        _Pragma("unroll")                                                           \
        for (int i = 0; i < 4; i++) {                                               \
            int f = tid + i * GT;                                                   \
            int row = f >> 3, seg = f & 7;                                          \
            CP_ASYNC16(ab + (uint32_t)(row * PADK + seg * 4) * 4,                   \
                       Aglob + (size_t)(r0 + row) * D + (cc) * BK + seg * 4);       \
        }                                                                           \
        _Pragma("unroll")                                                           \
        for (int i = 0; i < 8; i++) {                                               \
            int f = tid + i * GT;                                                   \
            int row = f >> 3, seg = f & 7;                                          \
            CP_ASYNC16(bb + (uint32_t)(row * PADK + seg * 4) * 4,                   \
                       Wm + (size_t)(c0 + row) * D + (cc) * BK + seg * 4);          \
        }                                                                           \
        CP_COMMIT();                                                                \
    } while (0)

    // prologue: stages 0 and 1
    STAGE_CHUNK(0, smb);
    STAGE_CHUNK(1, smb + SSB);

    const float* rs = smf;                 // read stage
    uint32_t ws = smb + 2u * SSB;          // write stage

    for (int c = 0; c < NCHUNK; ++c) {
        if (c + 1 < NCHUNK) { CP_WAIT(1); } else { CP_WAIT(0); }
        __syncthreads();
        if (c + 2 < NCHUNK) {
            STAGE_CHUNK(c + 2, ws);
            ws += SSB;
            if (ws == smb + 3u * SSB) ws = smb;
        }

        const float* As = rs;
        const float* Bs = rs + AF;
#pragma unroll
        for (int ks = 0; ks < 4; ++ks) {
            int k = ks * 8;
            uint32_t af[4][4], bf[8][2];
#pragma unroll
            for (int mt = 0; mt < 4; mt++) {
                int m = wm * 64 + mt * 16 + g;
                float2 a02 = *(const float2*)&As[m * PADK + k + 2 * t];
                float2 a13 = *(const float2*)&As[(m + 8) * PADK + k + 2 * t];
                af[mt][0] = __float_as_uint(a02.x);
                af[mt][1] = __float_as_uint(a13.x);
                af[mt][2] = __float_as_uint(a02.y);
                af[mt][3] = __float_as_uint(a13.y);
            }
#pragma unroll
            for (int nt = 0; nt < 8; nt++) {
                int n = wn * 64 + nt * 8 + g;
                float2 b01 = *(const float2*)&Bs[n * PADK + k + 2 * t];
                bf[nt][0] = __float_as_uint(b01.x);
                bf[nt][1] = __float_as_uint(b01.y);
            }
#pragma unroll
            for (int mt = 0; mt < 4; mt++)
#pragma unroll
                for (int nt = 0; nt < 8; nt++)
                    mma8(acc[mt][nt], af[mt], bf[nt]);
        }
        rs += SSTRIDE;
        if (rs == smf + 3 * SSTRIDE) rs = smf;
    }

#pragma unroll
    for (int mt = 0; mt < 4; mt++) {
#pragma unroll
        for (int nt = 0; nt < 8; nt++) {
            int cg = c0 + wn * 64 + nt * 8 + 2 * t;
            float b0 = bias[cg], b1 = bias[cg + 1];
#pragma unroll
            for (int half = 0; half < 2; half++) {
                int rg = r0 + wm * 64 + mt * 16 + g + half * 8;
                float v0 = acc[mt][nt][half * 2 + 0] + b0;
                float v1 = acc[mt][nt][half * 2 + 1] + b1;
                if (head_layout) {
                    // q/k/v stored dk-permuted (perm3 within 8) for attention frags
                    int bb = rg >> 9, n = rg & 511;
                    int hh = cg >> 6;
                    int dk0 = cg & 63, dk1 = dk0 + 1;
                    float* base = outp + (((size_t)(bb * H + hh) * N + n) * DK);
                    base[(dk0 & ~7) | perm3(dk0 & 7)] = to_tf32(v0);
                    base[(dk1 & ~7) | perm3(dk1 & 7)] = to_tf32(v1);
                } else {
                    float* dst = outp + (size_t)rg * D + cg;
                    *(float2*)dst = make_float2(v0, v1);
                }
            }
        }
    }
}

// ================ attention with mma.sync tf32 + fused distance bias ================
// 512 threads, 16 warps (4x4). CTA = one (b,h) x 64 q rows. 3-buffer K/V pipeline.
// Q/K stored dk-permuted -> phase-1 fragment loads are LDS.64.
#define AT 512
#define PADA 72
#define PADS 516
#define KVF (64 * PADA)                       // 4608 floats per K/V buffer
#define QS_OFF 0
#define KB_OFF KVF                            // first of 3 buffers
#define SC_OFF (4 * KVF)                      // 18432
#define LUT_OFF (SC_OFF + 64 * PADS)          // 51456
#define PK_OFF  (LUT_OFF + 448)               // 51904
#define ATT_SMEM ((PK_OFF + 256) * 4)         // 208640 bytes

__device__ __forceinline__ void load_chunk64(uint32_t dst_base, const float* src) {
    int tid = threadIdx.x;
#pragma unroll
    for (int it = 0; it < 2; ++it) {
        int idx = tid + it * AT;
        int row = idx >> 4, seg = idx & 15;
        CP_ASYNC16(dst_base + (uint32_t)(row * PADA + seg * 4) * 4, src + idx * 4);
    }
}

__global__ void __launch_bounds__(AT, 1) attn_mma(const float* __restrict__ dist_emb,
                                                  float* __restrict__ att_out) {
    extern __shared__ float sm[];
    uint32_t smb = smem_u32(sm);
    float* Qs = sm + QS_OFF;
    float* Sc = sm + SC_OFF;
    float* lut = sm + LUT_OFF;
    unsigned short* pk = (unsigned short*)(sm + PK_OFF);

    int tid = threadIdx.x;
    int bh = blockIdx.y;
    int b = bh / H;
    int h = bh - b * H;
    int q0 = blockIdx.x * 64;

    const float* Qg = g_q + ((size_t)bh * N + q0) * DK;
    const float* Kg = g_k + (size_t)bh * N * DK;
    const float* Vg = g_v + (size_t)bh * N * DK;

    int lane = tid & 31, wid = tid >> 5;
    int wm = wid >> 2, wn = wid & 3;      // 4 x 4
    int g = lane >> 2, t = lane & 3;
    const float scale = 0.125f;

    uint32_t kb0 = smb + KB_OFF * 4;      // 3 consecutive buffers of KVF floats

    // prologue: Q + K0 (one group), K1 (second group)
    load_chunk64(smb + QS_OFF * 4, Qg);
    load_chunk64(kb0, Kg);
    CP_COMMIT();
    load_chunk64(kb0 + KVF * 4, Kg + 4096);
    CP_COMMIT();

    // distance-bias LUT (441 entries) + packed patch coords
    if (tid < 441) {
        int dyc = tid / 21 - 10, dxc = tid % 21 - 10;
        int bin = (int)(sqrtf((float)(dxc * dxc + dyc * dyc)) * 2.0f);
        lut[tid] = dist_emb[bin * H + h];
    }
    pk[tid] = (unsigned short)(g_py[b * N + tid] * 21 + g_px[b * N + tid]);

    // ---------- phase 1: S = Q K^T * scale ----------
    {
        const float* rk = sm + KB_OFF;
        uint32_t wk = kb0 + 2u * KVF * 4;
        for (int kt = 0; kt < 8; ++kt) {
            if (kt + 1 < 8) { CP_WAIT(1); } else { CP_WAIT(0); }
            __syncthreads();
            if (kt + 2 < 8) {
                load_chunk64(wk, Kg + (kt + 2) * 4096);
                CP_COMMIT();
                wk += KVF * 4;
                if (wk == kb0 + 3u * KVF * 4) wk = kb0;
            }
            const float* Ks = rk;
            float acc[2][4];
#pragma unroll
            for (int j = 0; j < 2; j++)
#pragma unroll
                for (int r = 0; r < 4; r++) acc[j][r] = 0.f;
#pragma unroll
            for (int ks = 0; ks < 8; ++ks) {
                int k = ks * 8;
                uint32_t af[4], bf[2][2];
                {
                    int m = wm * 16 + g;
                    float2 a02 = *(const float2*)&Qs[m * PADA + k + 2 * t];
                    float2 a13 = *(const float2*)&Qs[(m + 8) * PADA + k + 2 * t];
                    af[0] = __float_as_uint(a02.x);
                    af[1] = __float_as_uint(a13.x);
                    af[2] = __float_as_uint(a02.y);
                    af[3] = __float_as_uint(a13.y);
                }
#pragma unroll
                for (int nt = 0; nt < 2; nt++) {
                    int n = wn * 16 + nt * 8 + g;
                    float2 b01 = *(const float2*)&Ks[n * PADA + k + 2 * t];
                    bf[nt][0] = __float_as_uint(b01.x);
                    bf[nt][1] = __float_as_uint(b01.y);
                }
#pragma unroll
                for (int nt = 0; nt < 2; nt++)
                    mma8(acc[nt], af, bf[nt]);
            }
#pragma unroll
            for (int nt = 0; nt < 2; nt++) {
                int row = wm * 16 + g;
                int col = kt * 64 + wn * 16 + nt * 8 + 2 * t;
                *(float2*)&Sc[row * PADS + col] =
                    make_float2(acc[nt][0] * scale, acc[nt][1] * scale);
                *(float2*)&Sc[(row + 8) * PADS + col] =
                    make_float2(acc[nt][2] * scale, acc[nt][3] * scale);
            }
            rk += KVF;
            if (rk == sm + KB_OFF + 3 * KVF) rk = sm + KB_OFF;
        }
    }
    __syncthreads();   // Sc complete; K buffers idle

    // prefetch V chunks 0,1 — cp.async flight overlaps the softmax below
    load_chunk64(kb0, Vg);
    CP_COMMIT();
    load_chunk64(kb0 + KVF * 4, Vg + 4096);
    CP_COMMIT();

    // ---------- phase 2: 2-pass softmax, float4-vectorized ----------
#pragma unroll
    for (int rr = 0; rr < 4; rr++) {
        int qi = wid * 4 + rr;
        int qg = q0 + qi;
        int coff = 220 - (int)pk[qg];
        float* srow = Sc + qi * PADS;
        float ssum = 0.f;
#pragma unroll
        for (int i = 0; i < 4; i++) {
            int kk = lane * 4 + 128 * i;
            float4 s4 = *(const float4*)&srow[kk];
            ushort4 p4 = *(const ushort4*)&pk[kk];
            float e0 = __expf(s4.x + lut[(int)p4.x + coff]);
            float e1 = __expf(s4.y + lut[(int)p4.y + coff]);
            float e2 = __expf(s4.z + lut[(int)p4.z + coff]);
            float e3 = __expf(s4.w + lut[(int)p4.w + coff]);
            *(float4*)&srow[kk] = make_float4(e0, e1, e2, e3);
            ssum += (e0 + e1) + (e2 + e3);
        }
#pragma unroll
        for (int o = 16; o; o >>= 1) ssum += __shfl_xor_sync(~0u, ssum, o);
        float inv = 1.0f / ssum;
        float* arow = att_out + ((size_t)bh * N + qg) * N;
#pragma unroll
        for (int i = 0; i < 4; i++) {
            int kk = lane * 4 + 128 * i;
            float4 e4 = *(const float4*)&srow[kk];
            float4 p4 = make_float4(e4.x * inv, e4.y * inv, e4.z * inv, e4.w * inv);
            *(float4*)&arow[kk] = p4;
            *(float4*)&srow[kk] = make_float4(to_tf32(p4.x), to_tf32(p4.y),
                                              to_tf32(p4.z), to_tf32(p4.w));
        }
    }

    // ---------- phase 3: O = P V ----------
    float oacc[2][4];
#pragma unroll
    for (int j = 0; j < 2; j++)
#pragma unroll
        for (int r = 0; r < 4; r++) oacc[j][r] = 0.f;

    {
        const float* rv = sm + KB_OFF;
        uint32_t wv = kb0 + 2u * KVF * 4;
        for (int kt = 0; kt < 8; ++kt) {
            if (kt + 1 < 8) { CP_WAIT(1); } else { CP_WAIT(0); }
            __syncthreads();   // kt=0: also orders phase-2 Sc writes before fragment reads
            if (kt + 2 < 8) {
                load_chunk64(wv, Vg + (kt + 2) * 4096);
                CP_COMMIT();
                wv += KVF * 4;
                if (wv == kb0 + 3u * KVF * 4) wv = kb0;
            }
            const float* Vs = rv;
#pragma unroll
            for (int ks = 0; ks < 8; ++ks) {
                int k = ks * 8;
                uint32_t af[4], bf[2][2];
                {
                    int m = wm * 16 + g;
                    int sb = m * PADS + kt * 64 + k;
                    af[0] = __float_as_uint(Sc[sb + t]);
                    af[1] = __float_as_uint(Sc[sb + 8 * PADS + t]);
                    af[2] = __float_as_uint(Sc[sb + t + 4]);
                    af[3] = __float_as_uint(Sc[sb + 8 * PADS + t + 4]);
                }
#pragma unroll
                for (int nt = 0; nt < 2; nt++) {
                    int n = wn * 16 + nt * 8 + g;
                    bf[nt][0] = __float_as_uint(Vs[(k + t) * PADA + n]);
                    bf[nt][1] = __float_as_uint(Vs[(k + t + 4) * PADA + n]);
                }
#pragma unroll
                for (int nt = 0; nt < 2; nt++)
                    mma8(oacc[nt], af, bf[nt]);
            }
            rv += KVF;
            if (rv == sm + KB_OFF + 3 * KVF) rv = sm + KB_OFF;
        }
    }

    // epilogue: V cols were dk-permuted, so O cols come out permuted — exactly the
    // layout out-proj's A operand wants; store contiguously.
#pragma unroll
    for (int nt = 0; nt < 2; nt++) {
        int dk = wn * 16 + nt * 8 + 2 * t;
#pragma unroll
        for (int half = 0; half < 2; half++) {
            int qg = q0 + wm * 16 + g + half * 8;
            float* dst = g_ao + ((size_t)(b * N + qg)) * D + h * DK + dk;
            *(float2*)dst = make_float2(to_tf32(oacc[nt][half * 2 + 0]),
                                        to_tf32(oacc[nt][half * 2 + 1]));
        }
    }
}

// ---------------- launch ----------------
extern "C" void kernel_launch(void* const* d_in, const int* in_sizes, int n_in,
                              void* d_out, int out_size) {
    const float* features = (const float*)d_in[0];
    const float* boxes    = (const float*)d_in[1];
    const int*   iszs     = (const int*)  d_in[2];
    const float* Wq = (const float*)d_in[3];
    const float* bq = (const float*)d_in[4];
    const float* Wk = (const float*)d_in[5];
    const float* bk = (const float*)d_in[6];
    const float* Wv = (const float*)d_in[7];
    const float* bv = (const float*)d_in[8];
    const float* Wo = (const float*)d_in[9];
    const float* bo = (const float*)d_in[10];
    const float* gamma = (const float*)d_in[11];
    const float* beta  = (const float*)d_in[12];
    const float* dist_emb = (const float*)d_in[13];

    float* out = (float*)d_out;
    float* att = ((size_t)out_size >= OUT_ELEMS + ATT_ELEMS) ? out + OUT_ELEMS : out;

    cudaFuncSetAttribute(attn_mma, cudaFuncAttributeMaxDynamicSharedMemorySize, ATT_SMEM);
    cudaFuncSetAttribute(gemm_mma, cudaFuncAttributeMaxDynamicSharedMemorySize, GEMM_SMEM);

    float *gx, *gq, *gk, *gv, *gao;
    cudaGetSymbolAddress((void**)&gx, g_x);
    cudaGetSymbolAddress((void**)&gq, g_q);
    cudaGetSymbolAddress((void**)&gk, g_k);
    cudaGetSymbolAddress((void**)&gv, g_v);
    cudaGetSymbolAddress((void**)&gao, g_ao);

    ln_kernel<<<ROWS, 256>>>(features, gamma, beta);
    cvt_w<<<dim3((D * D) / 256, 4), 256>>>(Wq, Wk, Wv, Wo);
    patch_kernel<<<(ROWS + 255) / 256, 256>>>(boxes, iszs);

    dim3 gq3(D / BN, ROWS / BM, 3);
    gemm_mma<<<gq3, GT, GEMM_SMEM>>>(gx, bq, gq, bk, gk, bv, gv, 0, 1);

    dim3 ga(N / 64, B * H);
    attn_mma<<<ga, AT, ATT_SMEM>>>(dist_emb, att);

    dim3 go3(D / BN, ROWS / BM, 1);
    gemm_mma<<<go3, GT, GEMM_SMEM>>>(gao, bo, out, bo, out, bo, out, 3, 0);
}

// round 14
// speedup vs baseline: 1.1836x; 1.0208x over previous
#include <cuda_runtime.h>
#include <math.h>
#include <stdint.h>

#define B 16
#define N 512
#define D 768
#define H 12
#define DK 64
#define ND 32
#define ROWS (B * N)
#define OUT_ELEMS ((size_t)B * N * D)
#define ATT_ELEMS ((size_t)B * H * N * N)

// ---------------- scratch ----------------
__device__ float g_x[ROWS * D];
__device__ float g_q[ROWS * D];
__device__ float g_k[ROWS * D];
__device__ float g_v[ROWS * D];
__device__ float g_ao[ROWS * D];
__device__ float g_wt[4 * D * D];
__device__ int g_px[ROWS];
__device__ int g_py[ROWS];

__device__ __forceinline__ float to_tf32(float x) {
    uint32_t u;
    asm("cvt.rna.tf32.f32 %0, %1;" : "=r"(u) : "f"(x));
    return __uint_as_float(u);
}
// within-8 column permutation: k -> 2*(k&3) + (k>>2); maps (t, t+4) -> (2t, 2t+1)
__device__ __forceinline__ int perm3(int x) { return ((x & 3) << 1) | (x >> 2); }

__device__ __forceinline__ uint32_t smem_u32(const void* p) {
    uint32_t a;
    asm("{ .reg .u64 t; cvta.to.shared.u64 t, %1; cvt.u32.u64 %0, t; }" : "=r"(a) : "l"(p));
    return a;
}
#define CP_ASYNC16(dst, src) asm volatile("cp.async.cg.shared.global [%0], [%1], 16;" :: "r"(dst), "l"(src) : "memory")
#define CP_COMMIT()          asm volatile("cp.async.commit_group;" ::: "memory")
#define CP_WAIT(nn)          asm volatile("cp.async.wait_group %0;" :: "n"(nn) : "memory")

__device__ __forceinline__ void mma8(float* d, const uint32_t* a, const uint32_t* b) {
    asm volatile("mma.sync.aligned.m16n8k8.row.col.f32.tf32.tf32.f32 "
                 "{%0,%1,%2,%3}, {%4,%5,%6,%7}, {%8,%9}, {%0,%1,%2,%3};"
                 : "+f"(d[0]), "+f"(d[1]), "+f"(d[2]), "+f"(d[3])
                 : "r"(a[0]), "r"(a[1]), "r"(a[2]), "r"(a[3]), "r"(b[0]), "r"(b[1]));
}

// ---------------- LayerNorm (writes tf32-rounded, column-permuted) ----------------
__global__ void __launch_bounds__(256) ln_kernel(const float* __restrict__ f,
                                                 const float* __restrict__ gamma,
                                                 const float* __restrict__ beta) {
    int row = blockIdx.x;
    int t = threadIdx.x;
    const float* x = f + (size_t)row * D;
    float v[3];
    float s = 0.f, s2 = 0.f;
#pragma unroll
    for (int i = 0; i < 3; i++) {
        v[i] = x[t + i * 256];
        s += v[i];
        s2 += v[i] * v[i];
    }
    __shared__ float redA[8], redB[8];
#pragma unroll
    for (int o = 16; o; o >>= 1) {
        s += __shfl_xor_sync(~0u, s, o);
        s2 += __shfl_xor_sync(~0u, s2, o);
    }
    if ((t & 31) == 0) { redA[t >> 5] = s; redB[t >> 5] = s2; }
    __syncthreads();
    if (t < 32) {
        float a = (t < 8) ? redA[t] : 0.f;
        float c = (t < 8) ? redB[t] : 0.f;
#pragma unroll
        for (int o = 4; o; o >>= 1) {
            a += __shfl_xor_sync(~0u, a, o);
            c += __shfl_xor_sync(~0u, c, o);
        }
        if (t == 0) { redA[0] = a; redB[0] = c; }
    }
    __syncthreads();
    float mu = redA[0] * (1.0f / D);
    float var = redB[0] * (1.0f / D) - mu * mu;
    float rstd = rsqrtf(var + 1e-5f);
    float* xo = g_x + (size_t)row * D;
#pragma unroll
    for (int i = 0; i < 3; i++) {
        int c = t + i * 256;
        int cp = (c & ~7) | perm3(c & 7);
        xo[cp] = to_tf32((v[i] - mu) * rstd * gamma[c] + beta[c]);
    }
}

// weights: tf32-round + permute K columns
__global__ void __launch_bounds__(256) cvt_w(const float* __restrict__ Wq,
                                             const float* __restrict__ Wk,
                                             const float* __restrict__ Wv,
                                             const float* __restrict__ Wo) {
    int i = blockIdx.x * 256 + threadIdx.x;
    int z = blockIdx.y;
    const float* src = (z == 0) ? Wq : (z == 1) ? Wk : (z == 2) ? Wv : Wo;
    int ip = (i & ~7) | perm3(i & 7);
    g_wt[(size_t)z * D * D + ip] = to_tf32(src[i]);
}

__global__ void patch_kernel(const float* __restrict__ boxes,
                             const int* __restrict__ iszs) {
    int idx = blockIdx.x * 256 + threadIdx.x;
    if (idx >= ROWS) return;
    int b = idx >> 9;
    float w = (float)iszs[b * 4 + 0];
    float h = (float)iszs[b * 4 + 1];
    const float* bx = boxes + (size_t)idx * 4;
    float p0 = bx[0] * w, p1 = bx[1] * h, p2 = bx[2] * w, p3 = bx[3] * h;
    float spw = floorf(w / 11.0f);
    float sph = floorf(h / 11.0f);
    float cx = floorf((p0 + p2) * 0.5f);
    float cy = floorf((p1 + p3) * 0.5f);
    int px = 0, py = 0;
    bool fx = false, fy = false;
#pragma unroll
    for (int j = 0; j < 11; j++) {
        float jl = (float)j, jh = (float)(j + 1);
        float lo = jl * spw, hi = jh * spw;
        if (!fx && lo <= cx && cx <= hi) { px = j; fx = true; }
        float lo2 = jl * sph, hi2 = jh * sph;
        if (!fy && lo2 <= cy && cy <= hi2) { py = j; fy = true; }
    }
    g_px[idx] = px;
    g_py[idx] = py;
}

// ================ mma.sync tf32 GEMM: C[8192,768] = A @ W^T + bias ================
#define BM 128
#define BN 256
#define BK 32
#define PADK 40
#define AF (BM * PADK)
#define BF (BN * PADK)
#define SSTRIDE (AF + BF)
#define SSB (SSTRIDE * 4)
#define NCHUNK (D / BK)
#define GEMM_SMEM (3 * SSB)
#define GT 256

__global__ void __launch_bounds__(GT, 1)
gemm_mma(const float* __restrict__ Aglob,
         const float* __restrict__ b0v, float* __restrict__ o0,
         const float* __restrict__ b1v, float* __restrict__ o1,
         const float* __restrict__ b2v, float* __restrict__ o2,
         int wsel, int head_layout) {
    extern __shared__ float smf[];
    uint32_t smb = smem_u32(smf);
    int tid = threadIdx.x;
    int z = blockIdx.z;
    const float* Wm = g_wt + (size_t)(wsel + z) * D * D;
    const float* bias = (z == 0) ? b0v : (z == 1) ? b1v : b2v;
    float* outp = (z == 0) ? o0 : (z == 1) ? o1 : o2;

    int r0 = blockIdx.y * BM;
    int c0 = blockIdx.x * BN;

    int lane = tid & 31, wid = tid >> 5;
    int wm = wid >> 2, wn = wid & 3;
    int g = lane >> 2, t = lane & 3;

    float acc[4][8][4];
#pragma unroll
    for (int i = 0; i < 4; i++)
#pragma unroll
        for (int j = 0; j < 8; j++)
#pragma unroll
            for (int r = 0; r < 4; r++) acc[i][j][r] = 0.f;

#define STAGE_CHUNK(cc, sbase)                                                      \
    do {                                                                            \
        uint32_t ab = (sbase);                                                      \
        uint32_t bb = (sbase) + AF * 4;                                             \
        _Pragma("unroll")                                                           \
        for (int i = 0; i < 4; i++) {                                               \
            int f = tid + i * GT;                                                   \
            int row = f >> 3, seg = f & 7;                                          \
            CP_ASYNC16(ab + (uint32_t)(row * PADK + seg * 4) * 4,                   \
                       Aglob + (size_t)(r0 + row) * D + (cc) * BK + seg * 4);       \
        }                                                                           \
        _Pragma("unroll")                                                           \
        for (int i = 0; i < 8; i++) {                                               \
            int f = tid + i * GT;                                                   \
            int row = f >> 3, seg = f & 7;                                          \
            CP_ASYNC16(bb + (uint32_t)(row * PADK + seg * 4) * 4,                   \
                       Wm + (size_t)(c0 + row) * D + (cc) * BK + seg * 4);          \
        }                                                                           \
        CP_COMMIT();                                                                \
    } while (0)

    STAGE_CHUNK(0, smb);
    STAGE_CHUNK(1, smb + SSB);

    const float* rs = smf;
    uint32_t ws = smb + 2u * SSB;

    for (int c = 0; c < NCHUNK; ++c) {
        if (c + 1 < NCHUNK) { CP_WAIT(1); } else { CP_WAIT(0); }
        __syncthreads();
        if (c + 2 < NCHUNK) {
            STAGE_CHUNK(c + 2, ws);
            ws += SSB;
            if (ws == smb + 3u * SSB) ws = smb;
        }

        const float* As = rs;
        const float* Bs = rs + AF;
#pragma unroll
        for (int ks = 0; ks < 4; ++ks) {
            int k = ks * 8;
            uint32_t af[4][4], bf[8][2];
#pragma unroll
            for (int mt = 0; mt < 4; mt++) {
                int m = wm * 64 + mt * 16 + g;
                float2 a02 = *(const float2*)&As[m * PADK + k + 2 * t];
                float2 a13 = *(const float2*)&As[(m + 8) * PADK + k + 2 * t];
                af[mt][0] = __float_as_uint(a02.x);
                af[mt][1] = __float_as_uint(a13.x);
                af[mt][2] = __float_as_uint(a02.y);
                af[mt][3] = __float_as_uint(a13.y);
            }
#pragma unroll
            for (int nt = 0; nt < 8; nt++) {
                int n = wn * 64 + nt * 8 + g;
                float2 b01 = *(const float2*)&Bs[n * PADK + k + 2 * t];
                bf[nt][0] = __float_as_uint(b01.x);
                bf[nt][1] = __float_as_uint(b01.y);
            }
#pragma unroll
            for (int mt = 0; mt < 4; mt++)
#pragma unroll
                for (int nt = 0; nt < 8; nt++)
                    mma8(acc[mt][nt], af[mt], bf[nt]);
        }
        rs += SSTRIDE;
        if (rs == smf + 3 * SSTRIDE) rs = smf;
    }

#pragma unroll
    for (int mt = 0; mt < 4; mt++) {
#pragma unroll
        for (int nt = 0; nt < 8; nt++) {
            int cg = c0 + wn * 64 + nt * 8 + 2 * t;
            float b0 = bias[cg], b1 = bias[cg + 1];
#pragma unroll
            for (int half = 0; half < 2; half++) {
                int rg = r0 + wm * 64 + mt * 16 + g + half * 8;
                float v0 = acc[mt][nt][half * 2 + 0] + b0;
                float v1 = acc[mt][nt][half * 2 + 1] + b1;
                if (head_layout) {
                    int bb = rg >> 9, n = rg & 511;
                    int hh = cg >> 6;
                    int dk0 = cg & 63, dk1 = dk0 + 1;
                    float* base = outp + (((size_t)(bb * H + hh) * N + n) * DK);
                    base[(dk0 & ~7) | perm3(dk0 & 7)] = to_tf32(v0);
                    base[(dk1 & ~7) | perm3(dk1 & 7)] = to_tf32(v1);
                } else {
                    float* dst = outp + (size_t)rg * D + cg;
                    *(float2*)dst = make_float2(v0, v1);
                }
            }
        }
    }
}

// ================ attention: 32-q-row tiles, 256 threads, 2 CTAs/SM ================
// 8 warps (2x4). 2-buffer K/V pipeline (2 syncs/chunk). smem ~112 KB.
#define AT 256
#define QT 32
#define PADA 72
#define PADS 516
#define KVF (64 * PADA)                       // 4608 floats per K/V buffer
#define QS_OFF 0                              // 32*72 = 2304
#define KB_OFF (QT * PADA)                    // 2304; 2 buffers
#define SC_OFF (KB_OFF + 2 * KVF)             // 11520; 32*516 = 16512
#define LUT_OFF (SC_OFF + QT * PADS)          // 28032
#define PK_OFF  (LUT_OFF + 448)               // 28480
#define ATT_SMEM ((PK_OFF + 256) * 4)         // 114944 bytes

__device__ __forceinline__ void load_chunk64(uint32_t dst_base, const float* src) {
    int tid = threadIdx.x;
#pragma unroll
    for (int it = 0; it < 4; ++it) {
        int idx = tid + it * AT;
        int row = idx >> 4, seg = idx & 15;
        CP_ASYNC16(dst_base + (uint32_t)(row * PADA + seg * 4) * 4, src + idx * 4);
    }
}

__global__ void __launch_bounds__(AT, 2) attn_mma(const float* __restrict__ dist_emb,
                                                  float* __restrict__ att_out) {
    extern __shared__ float sm[];
    uint32_t smb = smem_u32(sm);
    float* Qs = sm + QS_OFF;
    float* Sc = sm + SC_OFF;
    float* lut = sm + LUT_OFF;
    unsigned short* pk = (unsigned short*)(sm + PK_OFF);

    int tid = threadIdx.x;
    int bh = blockIdx.y;
    int b = bh / H;
    int h = bh - b * H;
    int q0 = blockIdx.x * QT;

    const float* Qg = g_q + ((size_t)bh * N + q0) * DK;
    const float* Kg = g_k + (size_t)bh * N * DK;
    const float* Vg = g_v + (size_t)bh * N * DK;

    int lane = tid & 31, wid = tid >> 5;
    int wm = wid >> 2, wn = wid & 3;      // 2 x 4
    int g = lane >> 2, t = lane & 3;
    const float scale = 0.125f;

    uint32_t kb0 = smb + KB_OFF * 4;      // 2 buffers of KVF floats

    // prologue: Q tile (32 rows)
    {
#pragma unroll
        for (int it = 0; it < 2; ++it) {
            int idx = tid + it * AT;
            int row = idx >> 4, seg = idx & 15;
            CP_ASYNC16(smb + (uint32_t)(QS_OFF + row * PADA + seg * 4) * 4, Qg + idx * 4);
        }
    }
    // K0, K1
    load_chunk64(kb0, Kg);
    CP_COMMIT();
    load_chunk64(kb0 + KVF * 4, Kg + 4096);
    CP_COMMIT();

    // distance-bias LUT (441; grid-stride over 256 threads) + packed patch coords
    for (int i = tid; i < 441; i += AT) {
        int dyc = i / 21 - 10, dxc = i % 21 - 10;
        int bin = (int)(sqrtf((float)(dxc * dxc + dyc * dyc)) * 2.0f);
        lut[i] = dist_emb[bin * H + h];
    }
    {
        int kk = tid * 2;
        pk[kk]     = (unsigned short)(g_py[b * N + kk] * 21 + g_px[b * N + kk]);
        pk[kk + 1] = (unsigned short)(g_py[b * N + kk + 1] * 21 + g_px[b * N + kk + 1]);
    }

    // ---------- phase 1: S = Q K^T * scale (2-buffer, 2-sync pipeline) ----------
    for (int kt = 0; kt < 8; ++kt) {
        if (kt < 7) { CP_WAIT(1); } else { CP_WAIT(0); }
        __syncthreads();
        const float* Ks = sm + KB_OFF + (kt & 1) * KVF;
        float acc[2][4];
#pragma unroll
        for (int j = 0; j < 2; j++)
#pragma unroll
            for (int r = 0; r < 4; r++) acc[j][r] = 0.f;
#pragma unroll
        for (int ks = 0; ks < 8; ++ks) {
            int k = ks * 8;
            uint32_t af[4], bf[2][2];
            {
                int m = wm * 16 + g;
                float2 a02 = *(const float2*)&Qs[m * PADA + k + 2 * t];
                float2 a13 = *(const float2*)&Qs[(m + 8) * PADA + k + 2 * t];
                af[0] = __float_as_uint(a02.x);
                af[1] = __float_as_uint(a13.x);
                af[2] = __float_as_uint(a02.y);
                af[3] = __float_as_uint(a13.y);
            }
#pragma unroll
            for (int nt = 0; nt < 2; nt++) {
                int n = wn * 16 + nt * 8 + g;
                float2 b01 = *(const float2*)&Ks[n * PADA + k + 2 * t];
                bf[nt][0] = __float_as_uint(b01.x);
                bf[nt][1] = __float_as_uint(b01.y);
            }
#pragma unroll
            for (int nt = 0; nt < 2; nt++)
                mma8(acc[nt], af, bf[nt]);
        }
#pragma unroll
        for (int nt = 0; nt < 2; nt++) {
            int row = wm * 16 + g;
            int col = kt * 64 + wn * 16 + nt * 8 + 2 * t;
            *(float2*)&Sc[row * PADS + col] =
                make_float2(acc[nt][0] * scale, acc[nt][1] * scale);
            *(float2*)&Sc[(row + 8) * PADS + col] =
                make_float2(acc[nt][2] * scale, acc[nt][3] * scale);
        }
        __syncthreads();
        if (kt + 2 < 8) {
            load_chunk64(kb0 + (kt & 1) * KVF * 4, Kg + (kt + 2) * 4096);
            CP_COMMIT();
        }
    }

    // prefetch V chunks 0,1 — flight overlaps softmax below
    load_chunk64(kb0, Vg);
    CP_COMMIT();
    load_chunk64(kb0 + KVF * 4, Vg + 4096);
    CP_COMMIT();

    // ---------- phase 2: 2-pass softmax, float4-vectorized ----------
#pragma unroll
    for (int rr = 0; rr < 4; rr++) {
        int qi = wid * 4 + rr;
        int qg = q0 + qi;
        int coff = 220 - (int)pk[qg];
        float* srow = Sc + qi * PADS;
        float ssum = 0.f;
#pragma unroll
        for (int i = 0; i < 4; i++) {
            int kk = lane * 4 + 128 * i;
            float4 s4 = *(const float4*)&srow[kk];
            ushort4 p4 = *(const ushort4*)&pk[kk];
            float e0 = __expf(s4.x + lut[(int)p4.x + coff]);
            float e1 = __expf(s4.y + lut[(int)p4.y + coff]);
            float e2 = __expf(s4.z + lut[(int)p4.z + coff]);
            float e3 = __expf(s4.w + lut[(int)p4.w + coff]);
            *(float4*)&srow[kk] = make_float4(e0, e1, e2, e3);
            ssum += (e0 + e1) + (e2 + e3);
        }
#pragma unroll
        for (int o = 16; o; o >>= 1) ssum += __shfl_xor_sync(~0u, ssum, o);
        float inv = 1.0f / ssum;
        float* arow = att_out + ((size_t)bh * N + qg) * N;
#pragma unroll
        for (int i = 0; i < 4; i++) {
            int kk = lane * 4 + 128 * i;
            float4 e4 = *(const float4*)&srow[kk];
            float4 p4 = make_float4(e4.x * inv, e4.y * inv, e4.z * inv, e4.w * inv);
            *(float4*)&arow[kk] = p4;
            *(float4*)&srow[kk] = make_float4(to_tf32(p4.x), to_tf32(p4.y),
                                              to_tf32(p4.z), to_tf32(p4.w));
        }
    }

    // ---------- phase 3: O = P V (2-buffer, 2-sync pipeline) ----------
    float oacc[2][4];
#pragma unroll
    for (int j = 0; j < 2; j++)
#pragma unroll
        for (int r = 0; r < 4; r++) oacc[j][r] = 0.f;

    for (int kt = 0; kt < 8; ++kt) {
        if (kt < 7) { CP_WAIT(1); } else { CP_WAIT(0); }
        __syncthreads();   // kt=0: also orders phase-2 Sc writes before fragment reads
        const float* Vs = sm + KB_OFF + (kt & 1) * KVF;
#pragma unroll
        for (int ks = 0; ks < 8; ++ks) {
            int k = ks * 8;
            uint32_t af[4], bf[2][2];
            {
                int m = wm * 16 + g;
                int sb = m * PADS + kt * 64 + k;
                af[0] = __float_as_uint(Sc[sb + t]);
                af[1] = __float_as_uint(Sc[sb + 8 * PADS + t]);
                af[2] = __float_as_uint(Sc[sb + t + 4]);
                af[3] = __float_as_uint(Sc[sb + 8 * PADS + t + 4]);
            }
#pragma unroll
            for (int nt = 0; nt < 2; nt++) {
                int n = wn * 16 + nt * 8 + g;
                bf[nt][0] = __float_as_uint(Vs[(k + t) * PADA + n]);
                bf[nt][1] = __float_as_uint(Vs[(k + t + 4) * PADA + n]);
            }
#pragma unroll
            for (int nt = 0; nt < 2; nt++)
                mma8(oacc[nt], af, bf[nt]);
        }
        __syncthreads();
        if (kt + 2 < 8) {
            load_chunk64(kb0 + (kt & 1) * KVF * 4, Vg + (kt + 2) * 4096);
            CP_COMMIT();
        }
    }

    // epilogue: V cols dk-permuted -> O cols permuted = out-proj's expected layout
#pragma unroll
    for (int nt = 0; nt < 2; nt++) {
        int dk = wn * 16 + nt * 8 + 2 * t;
#pragma unroll
        for (int half = 0; half < 2; half++) {
            int qg = q0 + wm * 16 + g + half * 8;
            float* dst = g_ao + ((size_t)(b * N + qg)) * D + h * DK + dk;
            *(float2*)dst = make_float2(to_tf32(oacc[nt][half * 2 + 0]),
                                        to_tf32(oacc[nt][half * 2 + 1]));
        }
    }
}

// ---------------- launch ----------------
extern "C" void kernel_launch(void* const* d_in, const int* in_sizes, int n_in,
                              void* d_out, int out_size) {
    const float* features = (const float*)d_in[0];
    const float* boxes    = (const float*)d_in[1];
    const int*   iszs     = (const int*)  d_in[2];
    const float* Wq = (const float*)d_in[3];
    const float* bq = (const float*)d_in[4];
    const float* Wk = (const float*)d_in[5];
    const float* bk = (const float*)d_in[6];
    const float* Wv = (const float*)d_in[7];
    const float* bv = (const float*)d_in[8];
    const float* Wo = (const float*)d_in[9];
    const float* bo = (const float*)d_in[10];
    const float* gamma = (const float*)d_in[11];
    const float* beta  = (const float*)d_in[12];
    const float* dist_emb = (const float*)d_in[13];

    float* out = (float*)d_out;
    float* att = ((size_t)out_size >= OUT_ELEMS + ATT_ELEMS) ? out + OUT_ELEMS : out;

    cudaFuncSetAttribute(attn_mma, cudaFuncAttributeMaxDynamicSharedMemorySize, ATT_SMEM);
    cudaFuncSetAttribute(gemm_mma, cudaFuncAttributeMaxDynamicSharedMemorySize, GEMM_SMEM);

    float *gx, *gq, *gk, *gv, *gao;
    cudaGetSymbolAddress((void**)&gx, g_x);
    cudaGetSymbolAddress((void**)&gq, g_q);
    cudaGetSymbolAddress((void**)&gk, g_k);
    cudaGetSymbolAddress((void**)&gv, g_v);
    cudaGetSymbolAddress((void**)&gao, g_ao);

    ln_kernel<<<ROWS, 256>>>(features, gamma, beta);
    cvt_w<<<dim3((D * D) / 256, 4), 256>>>(Wq, Wk, Wv, Wo);
    patch_kernel<<<(ROWS + 255) / 256, 256>>>(boxes, iszs);

    dim3 gq3(D / BN, ROWS / BM, 3);
    gemm_mma<<<gq3, GT, GEMM_SMEM>>>(gx, bq, gq, bk, gk, bv, gv, 0, 1);

    dim3 ga(N / QT, B * H);
    attn_mma<<<ga, AT, ATT_SMEM>>>(dist_emb, att);

    dim3 go3(D / BN, ROWS / BM, 1);
    gemm_mma<<<go3, GT, GEMM_SMEM>>>(gao, bo, out, bo, out, bo, out, 3, 0);
}

// round 15
// speedup vs baseline: 1.2458x; 1.0525x over previous
#include <cuda_runtime.h>
#include <math.h>
#include <stdint.h>

#define B 16
#define N 512
#define D 768
#define H 12
#define DK 64
#define ND 32
#define ROWS (B * N)
#define OUT_ELEMS ((size_t)B * N * D)
#define ATT_ELEMS ((size_t)B * H * N * N)

// ---------------- scratch ----------------
__device__ float g_x[ROWS * D];
__device__ float g_q[ROWS * D];
__device__ float g_k[ROWS * D];
__device__ float g_v[ROWS * D];
__device__ float g_ao[ROWS * D];
__device__ float g_wt[4 * D * D];
__device__ int g_px[ROWS];
__device__ int g_py[ROWS];

__device__ __forceinline__ float to_tf32(float x) {
    uint32_t u;
    asm("cvt.rna.tf32.f32 %0, %1;" : "=r"(u) : "f"(x));
    return __uint_as_float(u);
}
// within-8 column permutation: k -> 2*(k&3) + (k>>2); maps (t, t+4) -> (2t, 2t+1)
__device__ __forceinline__ int perm3(int x) { return ((x & 3) << 1) | (x >> 2); }

__device__ __forceinline__ uint32_t smem_u32(const void* p) {
    uint32_t a;
    asm("{ .reg .u64 t; cvta.to.shared.u64 t, %1; cvt.u32.u64 %0, t; }" : "=r"(a) : "l"(p));
    return a;
}
#define CP_ASYNC16(dst, src) asm volatile("cp.async.cg.shared.global [%0], [%1], 16;" :: "r"(dst), "l"(src) : "memory")
#define CP_COMMIT()          asm volatile("cp.async.commit_group;" ::: "memory")
#define CP_WAIT(nn)          asm volatile("cp.async.wait_group %0;" :: "n"(nn) : "memory")

__device__ __forceinline__ void mma8(float* d, const uint32_t* a, const uint32_t* b) {
    asm volatile("mma.sync.aligned.m16n8k8.row.col.f32.tf32.tf32.f32 "
                 "{%0,%1,%2,%3}, {%4,%5,%6,%7}, {%8,%9}, {%0,%1,%2,%3};"
                 : "+f"(d[0]), "+f"(d[1]), "+f"(d[2]), "+f"(d[3])
                 : "r"(a[0]), "r"(a[1]), "r"(a[2]), "r"(a[3]), "r"(b[0]), "r"(b[1]));
}

// ================ fused prep: LN rows + weight cvt/permute + patch bins ================
#define LNB ROWS                         // 8192 blocks
#define WB ((4 * D * D) / (256 * 8))     // 1152 blocks (8 floats/thread)
#define PB (ROWS / 256)                  // 32 blocks

__global__ void __launch_bounds__(256) prep_kernel(
    const float* __restrict__ f, const float* __restrict__ gamma, const float* __restrict__ beta,
    const float* __restrict__ Wq, const float* __restrict__ Wk,
    const float* __restrict__ Wv, const float* __restrict__ Wo,
    const float* __restrict__ boxes, const int* __restrict__ iszs) {
    __shared__ float redA[8], redB[8];
    int bx = blockIdx.x;
    int t = threadIdx.x;

    if (bx < LNB) {
        // -------- LayerNorm row --------
        int row = bx;
        const float* x = f + (size_t)row * D;
        float v[3];
        float s = 0.f, s2 = 0.f;
#pragma unroll
        for (int i = 0; i < 3; i++) {
            v[i] = x[t + i * 256];
            s += v[i];
            s2 += v[i] * v[i];
        }
#pragma unroll
        for (int o = 16; o; o >>= 1) {
            s += __shfl_xor_sync(~0u, s, o);
            s2 += __shfl_xor_sync(~0u, s2, o);
        }
        if ((t & 31) == 0) { redA[t >> 5] = s; redB[t >> 5] = s2; }
        __syncthreads();
        if (t < 32) {
            float a = (t < 8) ? redA[t] : 0.f;
            float c = (t < 8) ? redB[t] : 0.f;
#pragma unroll
            for (int o = 4; o; o >>= 1) {
                a += __shfl_xor_sync(~0u, a, o);
                c += __shfl_xor_sync(~0u, c, o);
            }
            if (t == 0) { redA[0] = a; redB[0] = c; }
        }
        __syncthreads();
        float mu = redA[0] * (1.0f / D);
        float var = redB[0] * (1.0f / D) - mu * mu;
        float rstd = rsqrtf(var + 1e-5f);
        float* xo = g_x + (size_t)row * D;
#pragma unroll
        for (int i = 0; i < 3; i++) {
            int c = t + i * 256;
            int cp = (c & ~7) | perm3(c & 7);
            xo[cp] = to_tf32((v[i] - mu) * rstd * gamma[c] + beta[c]);
        }
    } else if (bx < LNB + WB) {
        // -------- weight tf32 + perm, 8 floats/thread --------
        size_t i8 = ((size_t)(bx - LNB) * 256 + t) * 8;
        int z = (int)(i8 / (D * D));
        int off = (int)(i8 % (D * D));
        const float* src = (z == 0) ? Wq : (z == 1) ? Wk : (z == 2) ? Wv : Wo;
        float4 a = *(const float4*)(src + i8 - (size_t)z * D * D);
        float4 b = *(const float4*)(src + i8 - (size_t)z * D * D + 4);
        float* dst = g_wt + (size_t)z * D * D + off;
        // out[j] = in[(j&1)*4 + (j>>1)]
        *(float4*)dst = make_float4(to_tf32(a.x), to_tf32(b.x), to_tf32(a.y), to_tf32(b.y));
        *(float4*)(dst + 4) = make_float4(to_tf32(a.z), to_tf32(b.z), to_tf32(a.w), to_tf32(b.w));
    } else {
        // -------- patch bins --------
        int idx = (bx - LNB - WB) * 256 + t;
        int b = idx >> 9;
        float w = (float)iszs[b * 4 + 0];
        float h = (float)iszs[b * 4 + 1];
        const float* bxp = boxes + (size_t)idx * 4;
        float p0 = bxp[0] * w, p1 = bxp[1] * h, p2 = bxp[2] * w, p3 = bxp[3] * h;
        float spw = floorf(w / 11.0f);
        float sph = floorf(h / 11.0f);
        float cx = floorf((p0 + p2) * 0.5f);
        float cy = floorf((p1 + p3) * 0.5f);
        int px = 0, py = 0;
        bool fx = false, fy = false;
#pragma unroll
        for (int j = 0; j < 11; j++) {
            float jl = (float)j, jh = (float)(j + 1);
            float lo = jl * spw, hi = jh * spw;
            if (!fx && lo <= cx && cx <= hi) { px = j; fx = true; }
            float lo2 = jl * sph, hi2 = jh * sph;
            if (!fy && lo2 <= cy && cy <= hi2) { py = j; fy = true; }
        }
        g_px[idx] = px;
        g_py[idx] = py;
    }
}

// ================ mma.sync tf32 GEMM: C[8192,768] = A @ W^T + bias ================
// Templated on NT (warp n-tiles). BM=128, BN=4*NT*8. 8 warps (2x4), 3-stage pipeline.
#define BM 128
#define BK 32
#define PADK 40
#define AF (BM * PADK)
#define NCHUNK (D / BK)
#define GT 256

template <int NT>
__global__ void __launch_bounds__(GT, 1)
gemm_mma(const float* __restrict__ Aglob,
         const float* __restrict__ b0v, float* __restrict__ o0,
         const float* __restrict__ b1v, float* __restrict__ o1,
         const float* __restrict__ b2v, float* __restrict__ o2,
         int wsel, int head_layout) {
    constexpr int WCOLS = NT * 8;
    constexpr int BNt = 4 * WCOLS;
    constexpr int BFt = BNt * PADK;
    constexpr int SST = AF + BFt;       // floats per stage
    constexpr int SSBt = SST * 4;       // bytes per stage

    extern __shared__ float smf[];
    uint32_t smb = smem_u32(smf);
    int tid = threadIdx.x;
    int z = blockIdx.z;
    const float* Wm = g_wt + (size_t)(wsel + z) * D * D;
    const float* bias = (z == 0) ? b0v : (z == 1) ? b1v : b2v;
    float* outp = (z == 0) ? o0 : (z == 1) ? o1 : o2;

    int r0 = blockIdx.y * BM;
    int c0 = blockIdx.x * BNt;

    int lane = tid & 31, wid = tid >> 5;
    int wm = wid >> 2, wn = wid & 3;
    int g = lane >> 2, t = lane & 3;

    float acc[4][NT][4];
#pragma unroll
    for (int i = 0; i < 4; i++)
#pragma unroll
        for (int j = 0; j < NT; j++)
#pragma unroll
            for (int r = 0; r < 4; r++) acc[i][j][r] = 0.f;

    auto stage_chunk = [&](int cc, uint32_t sbase) {
        uint32_t ab = sbase;
        uint32_t bb = sbase + AF * 4;
#pragma unroll
        for (int i = 0; i < 4; i++) {
            int fidx = tid + i * GT;
            int row = fidx >> 3, seg = fidx & 7;
            CP_ASYNC16(ab + (uint32_t)(row * PADK + seg * 4) * 4,
                       Aglob + (size_t)(r0 + row) * D + cc * BK + seg * 4);
        }
#pragma unroll
        for (int i = 0; i < NT; i++) {
            int fidx = tid + i * GT;
            int row = fidx >> 3, seg = fidx & 7;
            CP_ASYNC16(bb + (uint32_t)(row * PADK + seg * 4) * 4,
                       Wm + (size_t)(c0 + row) * D + cc * BK + seg * 4);
        }
        CP_COMMIT();
    };

    stage_chunk(0, smb);
    stage_chunk(1, smb + SSBt);

    const float* rs = smf;
    uint32_t ws = smb + 2u * SSBt;

    for (int c = 0; c < NCHUNK; ++c) {
        if (c + 1 < NCHUNK) { CP_WAIT(1); } else { CP_WAIT(0); }
        __syncthreads();
        if (c + 2 < NCHUNK) {
            stage_chunk(c + 2, ws);
            ws += SSBt;
            if (ws == smb + 3u * SSBt) ws = smb;
        }

        const float* As = rs;
        const float* Bs = rs + AF;
#pragma unroll
        for (int ks = 0; ks < 4; ++ks) {
            int k = ks * 8;
            uint32_t af[4][4], bf[NT][2];
#pragma unroll
            for (int mt = 0; mt < 4; mt++) {
                int m = wm * 64 + mt * 16 + g;
                float2 a02 = *(const float2*)&As[m * PADK + k + 2 * t];
                float2 a13 = *(const float2*)&As[(m + 8) * PADK + k + 2 * t];
                af[mt][0] = __float_as_uint(a02.x);
                af[mt][1] = __float_as_uint(a13.x);
                af[mt][2] = __float_as_uint(a02.y);
                af[mt][3] = __float_as_uint(a13.y);
            }
#pragma unroll
            for (int nt = 0; nt < NT; nt++) {
                int n = wn * WCOLS + nt * 8 + g;
                float2 b01 = *(const float2*)&Bs[n * PADK + k + 2 * t];
                bf[nt][0] = __float_as_uint(b01.x);
                bf[nt][1] = __float_as_uint(b01.y);
            }
#pragma unroll
            for (int mt = 0; mt < 4; mt++)
#pragma unroll
                for (int nt = 0; nt < NT; nt++)
                    mma8(acc[mt][nt], af[mt], bf[nt]);
        }
        rs += SST;
        if (rs == smf + 3 * SST) rs = smf;
    }

#pragma unroll
    for (int mt = 0; mt < 4; mt++) {
#pragma unroll
        for (int nt = 0; nt < NT; nt++) {
            int cg = c0 + wn * WCOLS + nt * 8 + 2 * t;
            float b0 = bias[cg], b1 = bias[cg + 1];
#pragma unroll
            for (int half = 0; half < 2; half++) {
                int rg = r0 + wm * 64 + mt * 16 + g + half * 8;
                float v0 = acc[mt][nt][half * 2 + 0] + b0;
                float v1 = acc[mt][nt][half * 2 + 1] + b1;
                if (head_layout) {
                    int bb = rg >> 9, n = rg & 511;
                    int hh = cg >> 6;
                    int dk0 = cg & 63, dk1 = dk0 + 1;
                    float* base = outp + (((size_t)(bb * H + hh) * N + n) * DK);
                    base[(dk0 & ~7) | perm3(dk0 & 7)] = to_tf32(v0);
                    base[(dk1 & ~7) | perm3(dk1 & 7)] = to_tf32(v1);
                } else {
                    float* dst = outp + (size_t)rg * D + cg;
                    *(float2*)dst = make_float2(v0, v1);
                }
            }
        }
    }
}

#define GEMM_SMEM8 (3 * (AF + 256 * PADK) * 4)   // 184320
#define GEMM_SMEM6 (3 * (AF + 192 * PADK) * 4)   // 153600

// ================ attention: 32-q-row tiles, 256 threads, 2 CTAs/SM ================
#define AT 256
#define QT 32
#define PADA 72
#define PADS 516
#define KVF (64 * PADA)
#define QS_OFF 0
#define KB_OFF (QT * PADA)
#define SC_OFF (KB_OFF + 2 * KVF)
#define LUT_OFF (SC_OFF + QT * PADS)
#define PK_OFF  (LUT_OFF + 448)
#define ATT_SMEM ((PK_OFF + 256) * 4)

__device__ __forceinline__ void load_chunk64(uint32_t dst_base, const float* src) {
    int tid = threadIdx.x;
#pragma unroll
    for (int it = 0; it < 4; ++it) {
        int idx = tid + it * AT;
        int row = idx >> 4, seg = idx & 15;
        CP_ASYNC16(dst_base + (uint32_t)(row * PADA + seg * 4) * 4, src + idx * 4);
    }
}

__global__ void __launch_bounds__(AT, 2) attn_mma(const float* __restrict__ dist_emb,
                                                  float* __restrict__ att_out) {
    extern __shared__ float sm[];
    uint32_t smb = smem_u32(sm);
    float* Qs = sm + QS_OFF;
    float* Sc = sm + SC_OFF;
    float* lut = sm + LUT_OFF;
    unsigned short* pk = (unsigned short*)(sm + PK_OFF);

    int tid = threadIdx.x;
    int bh = blockIdx.y;
    int b = bh / H;
    int h = bh - b * H;
    int q0 = blockIdx.x * QT;

    const float* Qg = g_q + ((size_t)bh * N + q0) * DK;
    const float* Kg = g_k + (size_t)bh * N * DK;
    const float* Vg = g_v + (size_t)bh * N * DK;

    int lane = tid & 31, wid = tid >> 5;
    int wm = wid >> 2, wn = wid & 3;      // 2 x 4
    int g = lane >> 2, t = lane & 3;
    const float scale = 0.125f;

    uint32_t kb0 = smb + KB_OFF * 4;

    // prologue: Q tile (32 rows)
    {
#pragma unroll
        for (int it = 0; it < 2; ++it) {
            int idx = tid + it * AT;
            int row = idx >> 4, seg = idx & 15;
            CP_ASYNC16(smb + (uint32_t)(QS_OFF + row * PADA + seg * 4) * 4, Qg + idx * 4);
        }
    }
    load_chunk64(kb0, Kg);
    CP_COMMIT();
    load_chunk64(kb0 + KVF * 4, Kg + 4096);
    CP_COMMIT();

    for (int i = tid; i < 441; i += AT) {
        int dyc = i / 21 - 10, dxc = i % 21 - 10;
        int bin = (int)(sqrtf((float)(dxc * dxc + dyc * dyc)) * 2.0f);
        lut[i] = dist_emb[bin * H + h];
    }
    {
        int kk = tid * 2;
        pk[kk]     = (unsigned short)(g_py[b * N + kk] * 21 + g_px[b * N + kk]);
        pk[kk + 1] = (unsigned short)(g_py[b * N + kk + 1] * 21 + g_px[b * N + kk + 1]);
    }

    // ---------- phase 1: S = Q K^T * scale ----------
    for (int kt = 0; kt < 8; ++kt) {
        if (kt < 7) { CP_WAIT(1); } else { CP_WAIT(0); }
        __syncthreads();
        const float* Ks = sm + KB_OFF + (kt & 1) * KVF;
        float acc[2][4];
#pragma unroll
        for (int j = 0; j < 2; j++)
#pragma unroll
            for (int r = 0; r < 4; r++) acc[j][r] = 0.f;
#pragma unroll
        for (int ks = 0; ks < 8; ++ks) {
            int k = ks * 8;
            uint32_t af[4], bf[2][2];
            {
                int m = wm * 16 + g;
                float2 a02 = *(const float2*)&Qs[m * PADA + k + 2 * t];
                float2 a13 = *(const float2*)&Qs[(m + 8) * PADA + k + 2 * t];
                af[0] = __float_as_uint(a02.x);
                af[1] = __float_as_uint(a13.x);
                af[2] = __float_as_uint(a02.y);
                af[3] = __float_as_uint(a13.y);
            }
#pragma unroll
            for (int nt = 0; nt < 2; nt++) {
                int n = wn * 16 + nt * 8 + g;
                float2 b01 = *(const float2*)&Ks[n * PADA + k + 2 * t];
                bf[nt][0] = __float_as_uint(b01.x);
                bf[nt][1] = __float_as_uint(b01.y);
            }
#pragma unroll
            for (int nt = 0; nt < 2; nt++)
                mma8(acc[nt], af, bf[nt]);
        }
#pragma unroll
        for (int nt = 0; nt < 2; nt++) {
            int row = wm * 16 + g;
            int col = kt * 64 + wn * 16 + nt * 8 + 2 * t;
            *(float2*)&Sc[row * PADS + col] =
                make_float2(acc[nt][0] * scale, acc[nt][1] * scale);
            *(float2*)&Sc[(row + 8) * PADS + col] =
                make_float2(acc[nt][2] * scale, acc[nt][3] * scale);
        }
        __syncthreads();
        if (kt + 2 < 8) {
            load_chunk64(kb0 + (kt & 1) * KVF * 4, Kg + (kt + 2) * 4096);
            CP_COMMIT();
        }
    }

    // prefetch V chunks 0,1 — flight overlaps softmax
    load_chunk64(kb0, Vg);
    CP_COMMIT();
    load_chunk64(kb0 + KVF * 4, Vg + 4096);
    CP_COMMIT();

    // ---------- phase 2: 2-pass softmax, float4-vectorized ----------
#pragma unroll
    for (int rr = 0; rr < 4; rr++) {
        int qi = wid * 4 + rr;
        int qg = q0 + qi;
        int coff = 220 - (int)pk[qg];
        float* srow = Sc + qi * PADS;
        float ssum = 0.f;
#pragma unroll
        for (int i = 0; i < 4; i++) {
            int kk = lane * 4 + 128 * i;
            float4 s4 = *(const float4*)&srow[kk];
            ushort4 p4 = *(const ushort4*)&pk[kk];
            float e0 = __expf(s4.x + lut[(int)p4.x + coff]);
            float e1 = __expf(s4.y + lut[(int)p4.y + coff]);
            float e2 = __expf(s4.z + lut[(int)p4.z + coff]);
            float e3 = __expf(s4.w + lut[(int)p4.w + coff]);
            *(float4*)&srow[kk] = make_float4(e0, e1, e2, e3);
            ssum += (e0 + e1) + (e2 + e3);
        }
#pragma unroll
        for (int o = 16; o; o >>= 1) ssum += __shfl_xor_sync(~0u, ssum, o);
        float inv = 1.0f / ssum;
        float* arow = att_out + ((size_t)bh * N + qg) * N;
#pragma unroll
        for (int i = 0; i < 4; i++) {
            int kk = lane * 4 + 128 * i;
            float4 e4 = *(const float4*)&srow[kk];
            float4 p4 = make_float4(e4.x * inv, e4.y * inv, e4.z * inv, e4.w * inv);
            __stcs((float4*)&arow[kk], p4);   // streaming: att never re-read
            *(float4*)&srow[kk] = make_float4(to_tf32(p4.x), to_tf32(p4.y),
                                              to_tf32(p4.z), to_tf32(p4.w));
        }
    }

    // ---------- phase 3: O = P V ----------
    float oacc[2][4];
#pragma unroll
    for (int j = 0; j < 2; j++)
#pragma unroll
        for (int r = 0; r < 4; r++) oacc[j][r] = 0.f;

    for (int kt = 0; kt < 8; ++kt) {
        if (kt < 7) { CP_WAIT(1); } else { CP_WAIT(0); }
        __syncthreads();   // kt=0: also orders phase-2 Sc writes before fragment reads
        const float* Vs = sm + KB_OFF + (kt & 1) * KVF;
#pragma unroll
        for (int ks = 0; ks < 8; ++ks) {
            int k = ks * 8;
            uint32_t af[4], bf[2][2];
            {
                int m = wm * 16 + g;
                int sb = m * PADS + kt * 64 + k;
                af[0] = __float_as_uint(Sc[sb + t]);
                af[1] = __float_as_uint(Sc[sb + 8 * PADS + t]);
                af[2] = __float_as_uint(Sc[sb + t + 4]);
                af[3] = __float_as_uint(Sc[sb + 8 * PADS + t + 4]);
            }
#pragma unroll
            for (int nt = 0; nt < 2; nt++) {
                int n = wn * 16 + nt * 8 + g;
                bf[nt][0] = __float_as_uint(Vs[(k + t) * PADA + n]);
                bf[nt][1] = __float_as_uint(Vs[(k + t + 4) * PADA + n]);
            }
#pragma unroll
            for (int nt = 0; nt < 2; nt++)
                mma8(oacc[nt], af, bf[nt]);
        }
        __syncthreads();
        if (kt + 2 < 8) {
            load_chunk64(kb0 + (kt & 1) * KVF * 4, Vg + (kt + 2) * 4096);
            CP_COMMIT();
        }
    }

    // epilogue: V cols dk-permuted -> O cols permuted = out-proj's expected layout
#pragma unroll
    for (int nt = 0; nt < 2; nt++) {
        int dk = wn * 16 + nt * 8 + 2 * t;
#pragma unroll
        for (int half = 0; half < 2; half++) {
            int qg = q0 + wm * 16 + g + half * 8;
            float* dst = g_ao + ((size_t)(b * N + qg)) * D + h * DK + dk;
            *(float2*)dst = make_float2(to_tf32(oacc[nt][half * 2 + 0]),
                                        to_tf32(oacc[nt][half * 2 + 1]));
        }
    }
}

// ---------------- launch ----------------
extern "C" void kernel_launch(void* const* d_in, const int* in_sizes, int n_in,
                              void* d_out, int out_size) {
    const float* features = (const float*)d_in[0];
    const float* boxes    = (const float*)d_in[1];
    const int*   iszs     = (const int*)  d_in[2];
    const float* Wq = (const float*)d_in[3];
    const float* bq = (const float*)d_in[4];
    const float* Wk = (const float*)d_in[5];
    const float* bk = (const float*)d_in[6];
    const float* Wv = (const float*)d_in[7];
    const float* bv = (const float*)d_in[8];
    const float* Wo = (const float*)d_in[9];
    const float* bo = (const float*)d_in[10];
    const float* gamma = (const float*)d_in[11];
    const float* beta  = (const float*)d_in[12];
    const float* dist_emb = (const float*)d_in[13];

    float* out = (float*)d_out;
    float* att = ((size_t)out_size >= OUT_ELEMS + ATT_ELEMS) ? out + OUT_ELEMS : out;

    cudaFuncSetAttribute(attn_mma, cudaFuncAttributeMaxDynamicSharedMemorySize, ATT_SMEM);
    cudaFuncSetAttribute(gemm_mma<8>, cudaFuncAttributeMaxDynamicSharedMemorySize, GEMM_SMEM8);
    cudaFuncSetAttribute(gemm_mma<6>, cudaFuncAttributeMaxDynamicSharedMemorySize, GEMM_SMEM6);

    float *gx, *gq, *gk, *gv, *gao;
    cudaGetSymbolAddress((void**)&gx, g_x);
    cudaGetSymbolAddress((void**)&gq, g_q);
    cudaGetSymbolAddress((void**)&gk, g_k);
    cudaGetSymbolAddress((void**)&gv, g_v);
    cudaGetSymbolAddress((void**)&gao, g_ao);

    prep_kernel<<<LNB + WB + PB, 256>>>(features, gamma, beta, Wq, Wk, Wv, Wo, boxes, iszs);

    dim3 gq3(D / 256, ROWS / BM, 3);
    gemm_mma<8><<<gq3, GT, GEMM_SMEM8>>>(gx, bq, gq, bk, gk, bv, gv, 0, 1);

    dim3 ga(N / QT, B * H);
    attn_mma<<<ga, AT, ATT_SMEM>>>(dist_emb, att);

    dim3 go3(D / 192, ROWS / BM, 1);
    gemm_mma<6><<<go3, GT, GEMM_SMEM6>>>(gao, bo, out, bo, out, bo, out, 3, 0);
}

// round 16
// speedup vs baseline: 1.2512x; 1.0043x over previous
#include <cuda_runtime.h>
#include <math.h>
#include <stdint.h>

#define B 16
#define N 512
#define D 768
#define H 12
#define DK 64
#define ND 32
#define ROWS (B * N)
#define OUT_ELEMS ((size_t)B * N * D)
#define ATT_ELEMS ((size_t)B * H * N * N)

// ---------------- scratch ----------------
__device__ float g_x[ROWS * D];
__device__ float g_q[ROWS * D];
__device__ float g_k[ROWS * D];
__device__ float g_v[ROWS * D];
__device__ float g_ao[ROWS * D];
__device__ float g_wt[4 * D * D];
__device__ int g_px[ROWS];
__device__ int g_py[ROWS];

__device__ __forceinline__ float to_tf32(float x) {
    uint32_t u;
    asm("cvt.rna.tf32.f32 %0, %1;" : "=r"(u) : "f"(x));
    return __uint_as_float(u);
}
// within-8 column permutation: k -> 2*(k&3) + (k>>2); maps (t, t+4) -> (2t, 2t+1)
__device__ __forceinline__ int perm3(int x) { return ((x & 3) << 1) | (x >> 2); }

__device__ __forceinline__ uint32_t smem_u32(const void* p) {
    uint32_t a;
    asm("{ .reg .u64 t; cvta.to.shared.u64 t, %1; cvt.u32.u64 %0, t; }" : "=r"(a) : "l"(p));
    return a;
}
#define CP_ASYNC16(dst, src) asm volatile("cp.async.cg.shared.global [%0], [%1], 16;" :: "r"(dst), "l"(src) : "memory")
#define CP_COMMIT()          asm volatile("cp.async.commit_group;" ::: "memory")
#define CP_WAIT(nn)          asm volatile("cp.async.wait_group %0;" :: "n"(nn) : "memory")

__device__ __forceinline__ void mma8(float* d, const uint32_t* a, const uint32_t* b) {
    asm volatile("mma.sync.aligned.m16n8k8.row.col.f32.tf32.tf32.f32 "
                 "{%0,%1,%2,%3}, {%4,%5,%6,%7}, {%8,%9}, {%0,%1,%2,%3};"
                 : "+f"(d[0]), "+f"(d[1]), "+f"(d[2]), "+f"(d[3])
                 : "r"(a[0]), "r"(a[1]), "r"(a[2]), "r"(a[3]), "r"(b[0]), "r"(b[1]));
}

// ================ fused prep: LN rows + weight cvt/permute + patch bins ================
#define LNB ROWS                         // 8192 blocks
#define WB ((4 * D * D) / (256 * 8))     // 1152 blocks (8 floats/thread)
#define PB (ROWS / 256)                  // 32 blocks

__global__ void __launch_bounds__(256) prep_kernel(
    const float* __restrict__ f, const float* __restrict__ gamma, const float* __restrict__ beta,
    const float* __restrict__ Wq, const float* __restrict__ Wk,
    const float* __restrict__ Wv, const float* __restrict__ Wo,
    const float* __restrict__ boxes, const int* __restrict__ iszs) {
    __shared__ float redA[8], redB[8];
    int bx = blockIdx.x;
    int t = threadIdx.x;

    if (bx < LNB) {
        int row = bx;
        const float* x = f + (size_t)row * D;
        float v[3];
        float s = 0.f, s2 = 0.f;
#pragma unroll
        for (int i = 0; i < 3; i++) {
            v[i] = x[t + i * 256];
            s += v[i];
            s2 += v[i] * v[i];
        }
#pragma unroll
        for (int o = 16; o; o >>= 1) {
            s += __shfl_xor_sync(~0u, s, o);
            s2 += __shfl_xor_sync(~0u, s2, o);
        }
        if ((t & 31) == 0) { redA[t >> 5] = s; redB[t >> 5] = s2; }
        __syncthreads();
        if (t < 32) {
            float a = (t < 8) ? redA[t] : 0.f;
            float c = (t < 8) ? redB[t] : 0.f;
#pragma unroll
            for (int o = 4; o; o >>= 1) {
                a += __shfl_xor_sync(~0u, a, o);
                c += __shfl_xor_sync(~0u, c, o);
            }
            if (t == 0) { redA[0] = a; redB[0] = c; }
        }
        __syncthreads();
        float mu = redA[0] * (1.0f / D);
        float var = redB[0] * (1.0f / D) - mu * mu;
        float rstd = rsqrtf(var + 1e-5f);
        float* xo = g_x + (size_t)row * D;
#pragma unroll
        for (int i = 0; i < 3; i++) {
            int c = t + i * 256;
            int cp = (c & ~7) | perm3(c & 7);
            xo[cp] = to_tf32((v[i] - mu) * rstd * gamma[c] + beta[c]);
        }
    } else if (bx < LNB + WB) {
        size_t i8 = ((size_t)(bx - LNB) * 256 + t) * 8;
        int z = (int)(i8 / (D * D));
        int off = (int)(i8 % (D * D));
        const float* src = (z == 0) ? Wq : (z == 1) ? Wk : (z == 2) ? Wv : Wo;
        float4 a = *(const float4*)(src + i8 - (size_t)z * D * D);
        float4 b = *(const float4*)(src + i8 - (size_t)z * D * D + 4);
        float* dst = g_wt + (size_t)z * D * D + off;
        *(float4*)dst = make_float4(to_tf32(a.x), to_tf32(b.x), to_tf32(a.y), to_tf32(b.y));
        *(float4*)(dst + 4) = make_float4(to_tf32(a.z), to_tf32(b.z), to_tf32(a.w), to_tf32(b.w));
    } else {
        int idx = (bx - LNB - WB) * 256 + t;
        int b = idx >> 9;
        float w = (float)iszs[b * 4 + 0];
        float h = (float)iszs[b * 4 + 1];
        const float* bxp = boxes + (size_t)idx * 4;
        float p0 = bxp[0] * w, p1 = bxp[1] * h, p2 = bxp[2] * w, p3 = bxp[3] * h;
        float spw = floorf(w / 11.0f);
        float sph = floorf(h / 11.0f);
        float cx = floorf((p0 + p2) * 0.5f);
        float cy = floorf((p1 + p3) * 0.5f);
        int px = 0, py = 0;
        bool fx = false, fy = false;
#pragma unroll
        for (int j = 0; j < 11; j++) {
            float jl = (float)j, jh = (float)(j + 1);
            float lo = jl * spw, hi = jh * spw;
            if (!fx && lo <= cx && cx <= hi) { px = j; fx = true; }
            float lo2 = jl * sph, hi2 = jh * sph;
            if (!fy && lo2 <= cy && cy <= hi2) { py = j; fy = true; }
        }
        g_px[idx] = px;
        g_py[idx] = py;
    }
}

// ================ mma.sync tf32 GEMM: C = A @ W^T + bias ================
// BM=128, BN=128, BK=32. 8 warps (2x4), warp tile 64x32. 2-stage, 2 CTAs/SM.
#define BM 128
#define BNG 128
#define BK 32
#define PADK 40
#define AF (BM * PADK)                 // 5120 floats
#define BFG (BNG * PADK)               // 5120 floats
#define SSTG (AF + BFG)                // 10240 floats per stage
#define SSBG (SSTG * 4)                // 40960 bytes
#define NCHUNK (D / BK)                // 24
#define GEMM_SMEM (2 * SSBG)           // 81920 bytes
#define GT 256

__global__ void __launch_bounds__(GT, 2)
gemm_mma(const float* __restrict__ Aglob,
         const float* __restrict__ b0v, float* __restrict__ o0,
         const float* __restrict__ b1v, float* __restrict__ o1,
         const float* __restrict__ b2v, float* __restrict__ o2,
         int wsel, int head_layout) {
    extern __shared__ float smf[];
    uint32_t smb = smem_u32(smf);
    int tid = threadIdx.x;
    int z = blockIdx.z;
    const float* Wm = g_wt + (size_t)(wsel + z) * D * D;
    const float* bias = (z == 0) ? b0v : (z == 1) ? b1v : b2v;
    float* outp = (z == 0) ? o0 : (z == 1) ? o1 : o2;

    int r0 = blockIdx.y * BM;
    int c0 = blockIdx.x * BNG;

    int lane = tid & 31, wid = tid >> 5;
    int wm = wid >> 2, wn = wid & 3;       // 2 x 4; warp tile 64 x 32
    int g = lane >> 2, t = lane & 3;

    float acc[4][4][4];
#pragma unroll
    for (int i = 0; i < 4; i++)
#pragma unroll
        for (int j = 0; j < 4; j++)
#pragma unroll
            for (int r = 0; r < 4; r++) acc[i][j][r] = 0.f;

    auto stage_chunk = [&](int cc, uint32_t sbase) {
        uint32_t ab = sbase;
        uint32_t bb = sbase + AF * 4;
#pragma unroll
        for (int i = 0; i < 4; i++) {
            int fidx = tid + i * GT;
            int row = fidx >> 3, seg = fidx & 7;
            CP_ASYNC16(ab + (uint32_t)(row * PADK + seg * 4) * 4,
                       Aglob + (size_t)(r0 + row) * D + cc * BK + seg * 4);
        }
#pragma unroll
        for (int i = 0; i < 4; i++) {
            int fidx = tid + i * GT;
            int row = fidx >> 3, seg = fidx & 7;
            CP_ASYNC16(bb + (uint32_t)(row * PADK + seg * 4) * 4,
                       Wm + (size_t)(c0 + row) * D + cc * BK + seg * 4);
        }
        CP_COMMIT();
    };

    stage_chunk(0, smb);

    for (int c = 0; c < NCHUNK; ++c) {
        if (c + 1 < NCHUNK) {
            stage_chunk(c + 1, smb + ((c + 1) & 1) * SSBG);
            CP_WAIT(1);
        } else {
            CP_WAIT(0);
        }
        __syncthreads();

        const float* As = smf + (c & 1) * SSTG;
        const float* Bs = As + AF;
#pragma unroll
        for (int ks = 0; ks < 4; ++ks) {
            int k = ks * 8;
            uint32_t af[4][4], bf[4][2];
#pragma unroll
            for (int mt = 0; mt < 4; mt++) {
                int m = wm * 64 + mt * 16 + g;
                float2 a02 = *(const float2*)&As[m * PADK + k + 2 * t];
                float2 a13 = *(const float2*)&As[(m + 8) * PADK + k + 2 * t];
                af[mt][0] = __float_as_uint(a02.x);
                af[mt][1] = __float_as_uint(a13.x);
                af[mt][2] = __float_as_uint(a02.y);
                af[mt][3] = __float_as_uint(a13.y);
            }
#pragma unroll
            for (int nt = 0; nt < 4; nt++) {
                int n = wn * 32 + nt * 8 + g;
                float2 b01 = *(const float2*)&Bs[n * PADK + k + 2 * t];
                bf[nt][0] = __float_as_uint(b01.x);
                bf[nt][1] = __float_as_uint(b01.y);
            }
#pragma unroll
            for (int mt = 0; mt < 4; mt++)
#pragma unroll
                for (int nt = 0; nt < 4; nt++)
                    mma8(acc[mt][nt], af[mt], bf[nt]);
        }
        __syncthreads();
    }

#pragma unroll
    for (int mt = 0; mt < 4; mt++) {
#pragma unroll
        for (int nt = 0; nt < 4; nt++) {
            int cg = c0 + wn * 32 + nt * 8 + 2 * t;
            float b0 = bias[cg], b1 = bias[cg + 1];
#pragma unroll
            for (int half = 0; half < 2; half++) {
                int rg = r0 + wm * 64 + mt * 16 + g + half * 8;
                float v0 = acc[mt][nt][half * 2 + 0] + b0;
                float v1 = acc[mt][nt][half * 2 + 1] + b1;
                if (head_layout) {
                    int bb = rg >> 9, n = rg & 511;
                    int hh = cg >> 6;
                    int dk0 = cg & 63, dk1 = dk0 + 1;
                    float* base = outp + (((size_t)(bb * H + hh) * N + n) * DK);
                    base[(dk0 & ~7) | perm3(dk0 & 7)] = to_tf32(v0);
                    base[(dk1 & ~7) | perm3(dk1 & 7)] = to_tf32(v1);
                } else {
                    float* dst = outp + (size_t)rg * D + cg;
                    *(float2*)dst = make_float2(v0, v1);
                }
            }
        }
    }
}

// ================ attention: 32-q-row tiles, 256 threads, 2 CTAs/SM ================
#define AT 256
#define QT 32
#define PADA 72
#define PADS 516
#define KVF (64 * PADA)
#define QS_OFF 0
#define KB_OFF (QT * PADA)
#define SC_OFF (KB_OFF + 2 * KVF)
#define LUT_OFF (SC_OFF + QT * PADS)
#define PK_OFF  (LUT_OFF + 448)
#define ATT_SMEM ((PK_OFF + 256) * 4)

__device__ __forceinline__ void load_chunk64(uint32_t dst_base, const float* src) {
    int tid = threadIdx.x;
#pragma unroll
    for (int it = 0; it < 4; ++it) {
        int idx = tid + it * AT;
        int row = idx >> 4, seg = idx & 15;
        CP_ASYNC16(dst_base + (uint32_t)(row * PADA + seg * 4) * 4, src + idx * 4);
    }
}

__global__ void __launch_bounds__(AT, 2) attn_mma(const float* __restrict__ dist_emb,
                                                  float* __restrict__ att_out) {
    extern __shared__ float sm[];
    uint32_t smb = smem_u32(sm);
    float* Qs = sm + QS_OFF;
    float* Sc = sm + SC_OFF;
    float* lut = sm + LUT_OFF;
    unsigned short* pk = (unsigned short*)(sm + PK_OFF);

    int tid = threadIdx.x;
    int bh = blockIdx.y;
    int b = bh / H;
    int h = bh - b * H;
    int q0 = blockIdx.x * QT;

    const float* Qg = g_q + ((size_t)bh * N + q0) * DK;
    const float* Kg = g_k + (size_t)bh * N * DK;
    const float* Vg = g_v + (size_t)bh * N * DK;

    int lane = tid & 31, wid = tid >> 5;
    int wm = wid >> 2, wn = wid & 3;      // 2 x 4
    int g = lane >> 2, t = lane & 3;
    const float scale = 0.125f;

    uint32_t kb0 = smb + KB_OFF * 4;

    {
#pragma unroll
        for (int it = 0; it < 2; ++it) {
            int idx = tid + it * AT;
            int row = idx >> 4, seg = idx & 15;
            CP_ASYNC16(smb + (uint32_t)(QS_OFF + row * PADA + seg * 4) * 4, Qg + idx * 4);
        }
    }
    load_chunk64(kb0, Kg);
    CP_COMMIT();
    load_chunk64(kb0 + KVF * 4, Kg + 4096);
    CP_COMMIT();

    for (int i = tid; i < 441; i += AT) {
        int dyc = i / 21 - 10, dxc = i % 21 - 10;
        int bin = (int)(sqrtf((float)(dxc * dxc + dyc * dyc)) * 2.0f);
        lut[i] = dist_emb[bin * H + h];
    }
    {
        int kk = tid * 2;
        pk[kk]     = (unsigned short)(g_py[b * N + kk] * 21 + g_px[b * N + kk]);
        pk[kk + 1] = (unsigned short)(g_py[b * N + kk + 1] * 21 + g_px[b * N + kk + 1]);
    }

    // ---------- phase 1: S = Q K^T * scale ----------
    for (int kt = 0; kt < 8; ++kt) {
        if (kt < 7) { CP_WAIT(1); } else { CP_WAIT(0); }
        __syncthreads();
        const float* Ks = sm + KB_OFF + (kt & 1) * KVF;
        float acc[2][4];
#pragma unroll
        for (int j = 0; j < 2; j++)
#pragma unroll
            for (int r = 0; r < 4; r++) acc[j][r] = 0.f;
#pragma unroll
        for (int ks = 0; ks < 8; ++ks) {
            int k = ks * 8;
            uint32_t af[4], bf[2][2];
            {
                int m = wm * 16 + g;
                float2 a02 = *(const float2*)&Qs[m * PADA + k + 2 * t];
                float2 a13 = *(const float2*)&Qs[(m + 8) * PADA + k + 2 * t];
                af[0] = __float_as_uint(a02.x);
                af[1] = __float_as_uint(a13.x);
                af[2] = __float_as_uint(a02.y);
                af[3] = __float_as_uint(a13.y);
            }
#pragma unroll
            for (int nt = 0; nt < 2; nt++) {
                int n = wn * 16 + nt * 8 + g;
                float2 b01 = *(const float2*)&Ks[n * PADA + k + 2 * t];
                bf[nt][0] = __float_as_uint(b01.x);
                bf[nt][1] = __float_as_uint(b01.y);
            }
#pragma unroll
            for (int nt = 0; nt < 2; nt++)
                mma8(acc[nt], af, bf[nt]);
        }
#pragma unroll
        for (int nt = 0; nt < 2; nt++) {
            int row = wm * 16 + g;
            int col = kt * 64 + wn * 16 + nt * 8 + 2 * t;
            *(float2*)&Sc[row * PADS + col] =
                make_float2(acc[nt][0] * scale, acc[nt][1] * scale);
            *(float2*)&Sc[(row + 8) * PADS + col] =
                make_float2(acc[nt][2] * scale, acc[nt][3] * scale);
        }
        __syncthreads();
        if (kt + 2 < 8) {
            load_chunk64(kb0 + (kt & 1) * KVF * 4, Kg + (kt + 2) * 4096);
            CP_COMMIT();
        }
    }

    // prefetch V chunks 0,1 — flight overlaps softmax
    load_chunk64(kb0, Vg);
    CP_COMMIT();
    load_chunk64(kb0 + KVF * 4, Vg + 4096);
    CP_COMMIT();

    // ---------- phase 2: 2-pass softmax, float4-vectorized ----------
#pragma unroll
    for (int rr = 0; rr < 4; rr++) {
        int qi = wid * 4 + rr;
        int qg = q0 + qi;
        int coff = 220 - (int)pk[qg];
        float* srow = Sc + qi * PADS;
        float ssum = 0.f;
#pragma unroll
        for (int i = 0; i < 4; i++) {
            int kk = lane * 4 + 128 * i;
            float4 s4 = *(const float4*)&srow[kk];
            ushort4 p4 = *(const ushort4*)&pk[kk];
            float e0 = __expf(s4.x + lut[(int)p4.x + coff]);
            float e1 = __expf(s4.y + lut[(int)p4.y + coff]);
            float e2 = __expf(s4.z + lut[(int)p4.z + coff]);
            float e3 = __expf(s4.w + lut[(int)p4.w + coff]);
            *(float4*)&srow[kk] = make_float4(e0, e1, e2, e3);
            ssum += (e0 + e1) + (e2 + e3);
        }
#pragma unroll
        for (int o = 16; o; o >>= 1) ssum += __shfl_xor_sync(~0u, ssum, o);
        float inv = 1.0f / ssum;
        float* arow = att_out + ((size_t)bh * N + qg) * N;
#pragma unroll
        for (int i = 0; i < 4; i++) {
            int kk = lane * 4 + 128 * i;
            float4 e4 = *(const float4*)&srow[kk];
            float4 p4 = make_float4(e4.x * inv, e4.y * inv, e4.z * inv, e4.w * inv);
            __stcs((float4*)&arow[kk], p4);
            *(float4*)&srow[kk] = make_float4(to_tf32(p4.x), to_tf32(p4.y),
                                              to_tf32(p4.z), to_tf32(p4.w));
        }
    }

    // ---------- phase 3: O = P V ----------
    float oacc[2][4];
#pragma unroll
    for (int j = 0; j < 2; j++)
#pragma unroll
        for (int r = 0; r < 4; r++) oacc[j][r] = 0.f;

    for (int kt = 0; kt < 8; ++kt) {
        if (kt < 7) { CP_WAIT(1); } else { CP_WAIT(0); }
        __syncthreads();
        const float* Vs = sm + KB_OFF + (kt & 1) * KVF;
#pragma unroll
        for (int ks = 0; ks < 8; ++ks) {
            int k = ks * 8;
            uint32_t af[4], bf[2][2];
            {
                int m = wm * 16 + g;
                int sb = m * PADS + kt * 64 + k;
                af[0] = __float_as_uint(Sc[sb + t]);
                af[1] = __float_as_uint(Sc[sb + 8 * PADS + t]);
                af[2] = __float_as_uint(Sc[sb + t + 4]);
                af[3] = __float_as_uint(Sc[sb + 8 * PADS + t + 4]);
            }
#pragma unroll
            for (int nt = 0; nt < 2; nt++) {
                int n = wn * 16 + nt * 8 + g;
                bf[nt][0] = __float_as_uint(Vs[(k + t) * PADA + n]);
                bf[nt][1] = __float_as_uint(Vs[(k + t + 4) * PADA + n]);
            }
#pragma unroll
            for (int nt = 0; nt < 2; nt++)
                mma8(oacc[nt], af, bf[nt]);
        }
        __syncthreads();
        if (kt + 2 < 8) {
            load_chunk64(kb0 + (kt & 1) * KVF * 4, Vg + (kt + 2) * 4096);
            CP_COMMIT();
        }
    }

    // epilogue: V cols dk-permuted -> O cols permuted = out-proj's expected layout
#pragma unroll
    for (int nt = 0; nt < 2; nt++) {
        int dk = wn * 16 + nt * 8 + 2 * t;
#pragma unroll
        for (int half = 0; half < 2; half++) {
            int qg = q0 + wm * 16 + g + half * 8;
            float* dst = g_ao + ((size_t)(b * N + qg)) * D + h * DK + dk;
            *(float2*)dst = make_float2(to_tf32(oacc[nt][half * 2 + 0]),
                                        to_tf32(oacc[nt][half * 2 + 1]));
        }
    }
}

// ---------------- launch ----------------
extern "C" void kernel_launch(void* const* d_in, const int* in_sizes, int n_in,
                              void* d_out, int out_size) {
    const float* features = (const float*)d_in[0];
    const float* boxes    = (const float*)d_in[1];
    const int*   iszs     = (const int*)  d_in[2];
    const float* Wq = (const float*)d_in[3];
    const float* bq = (const float*)d_in[4];
    const float* Wk = (const float*)d_in[5];
    const float* bk = (const float*)d_in[6];
    const float* Wv = (const float*)d_in[7];
    const float* bv = (const float*)d_in[8];
    const float* Wo = (const float*)d_in[9];
    const float* bo = (const float*)d_in[10];
    const float* gamma = (const float*)d_in[11];
    const float* beta  = (const float*)d_in[12];
    const float* dist_emb = (const float*)d_in[13];

    float* out = (float*)d_out;
    float* att = ((size_t)out_size >= OUT_ELEMS + ATT_ELEMS) ? out + OUT_ELEMS : out;

    cudaFuncSetAttribute(attn_mma, cudaFuncAttributeMaxDynamicSharedMemorySize, ATT_SMEM);
    cudaFuncSetAttribute(gemm_mma, cudaFuncAttributeMaxDynamicSharedMemorySize, GEMM_SMEM);

    float *gx, *gq, *gk, *gv, *gao;
    cudaGetSymbolAddress((void**)&gx, g_x);
    cudaGetSymbolAddress((void**)&gq, g_q);
    cudaGetSymbolAddress((void**)&gk, g_k);
    cudaGetSymbolAddress((void**)&gv, g_v);
    cudaGetSymbolAddress((void**)&gao, g_ao);

    prep_kernel<<<LNB + WB + PB, 256>>>(features, gamma, beta, Wq, Wk, Wv, Wo, boxes, iszs);

    dim3 gq3(D / BNG, ROWS / BM, 3);
    gemm_mma<<<gq3, GT, GEMM_SMEM>>>(gx, bq, gq, bk, gk, bv, gv, 0, 1);

    dim3 ga(N / QT, B * H);
    attn_mma<<<ga, AT, ATT_SMEM>>>(dist_emb, att);

    dim3 go3(D / BNG, ROWS / BM, 1);
    gemm_mma<<<go3, GT, GEMM_SMEM>>>(gao, bo, out, bo, out, bo, out, 3, 0);
}